// round 6
// baseline (speedup 1.0000x reference)
#include <cuda_runtime.h>
#include <cuda_bf16.h>
#include <math.h>

#define NU 100000
#define NR 50000
#define NE 600000
#define NL 200000
#define HD 128
#define OD 64

typedef unsigned long long u64;

// ---------------- f32x2 packed math ----------------
__device__ __forceinline__ u64 fma2(u64 a, u64 b, u64 c) {
    u64 d;
    asm("fma.rn.f32x2 %0, %1, %2, %3;" : "=l"(d) : "l"(a), "l"(b), "l"(c));
    return d;
}
__device__ __forceinline__ float2 unpack2(u64 v) {
    float2 r; asm("mov.b64 {%0, %1}, %2;" : "=f"(r.x), "=f"(r.y) : "l"(v)); return r;
}

// ---------------- scratch ----------------
__device__ __align__(16) float g_hu[(size_t)NU * HD];
__device__ __align__(16) float g_hr[(size_t)NR * HD];
__device__ __align__(16) float g_p1[(size_t)NR * HD];
__device__ __align__(16) float g_u1[(size_t)NU * HD];
__device__ __align__(16) float g_r1[(size_t)NR * HD];
__device__ __align__(16) float g_mean_u[(size_t)NU * HD]; // mu, then U2
__device__ __align__(16) float g_mean_r[(size_t)NR * HD]; // mr, then R2
__device__ __align__(16) float g_zu[(size_t)NU * OD];
__device__ __align__(16) float g_zr[(size_t)NR * OD];
__device__ __align__(16) float g_wt[147456];

__device__ int g_deg_r[NR];
__device__ int g_deg_u[NU];
__device__ int g_off_r[NR + 1];
__device__ int g_off_u[NU + 1];
__device__ int g_cur_r[NR];
__device__ int g_cur_u[NU];
__device__ int g_csr_r[NE];
__device__ int g_csr_u[NE];

// all weights stored k-interleaved: [k/2][2*N] with (w_k, w_k+1) per column
#define WT_WU      0
#define WT_WREC    16384
#define WT_C1URWL  49152
#define WT_C1URWR  65536
#define WT_C1RUWL  81920
#define WT_C1RUWR  98304
#define WT_U2      114688   // cols 0-63 c2_ur_Wl^T, 64-127 c2_ru_Wr^T
#define WT_R2      131072   // cols 0-63 c2_ru_Wl^T, 64-127 c2_ur_Wr^T

// ---------------- CSR build ----------------
__global__ void zero_deg(int* __restrict__ deg_u, int* __restrict__ deg_r)
{
    int t = blockIdx.x * blockDim.x + threadIdx.x;
    if (t < NU) deg_u[t] = 0;
    if (t < NR) deg_r[t] = 0;
}

__global__ void count_kernel(const int* __restrict__ es, const int* __restrict__ ed,
                             int* __restrict__ deg_u, int* __restrict__ deg_r, int E)
{
    int t = blockIdx.x * blockDim.x + threadIdx.x;
    if (t < E) {
        atomicAdd(&deg_u[es[t]], 1);
        atomicAdd(&deg_r[ed[t]], 1);
    }
}

__global__ void scan2_kernel(const int* __restrict__ deg_r, int* __restrict__ off_r,
                             int* __restrict__ cur_r,
                             const int* __restrict__ deg_u, int* __restrict__ off_u,
                             int* __restrict__ cur_u)
{
    const int* deg; int* off; int* cur; int n;
    if (blockIdx.x == 0) { deg = deg_r; off = off_r; cur = cur_r; n = NR; }
    else                 { deg = deg_u; off = off_u; cur = cur_u; n = NU; }
    __shared__ int tmp[1024];
    int t = threadIdx.x;
    int chunk = (n + 1023) / 1024;
    int start = min(t * chunk, n);
    int end = min(start + chunk, n);
    int s = 0;
    for (int i = start; i < end; i++) s += deg[i];
    tmp[t] = s;
    __syncthreads();
    for (int d = 1; d < 1024; d <<= 1) {
        int v = (t >= d) ? tmp[t - d] : 0;
        __syncthreads();
        tmp[t] += v;
        __syncthreads();
    }
    int run = (t == 0) ? 0 : tmp[t - 1];
    for (int i = start; i < end; i++) {
        off[i] = run;
        cur[i] = run;
        run += deg[i];
    }
    if (end == n) off[n] = run;
}

__global__ void fill_kernel(const int* __restrict__ es, const int* __restrict__ ed,
                            int* __restrict__ cur_u, int* __restrict__ cur_r,
                            int* __restrict__ csr_u, int* __restrict__ csr_r, int E)
{
    int t = blockIdx.x * blockDim.x + threadIdx.x;
    if (t < E) {
        int s = es[t], d = ed[t];
        int pr = atomicAdd(&cur_r[d], 1);
        csr_r[pr] = s;
        int pu = atomicAdd(&cur_u[s], 1);
        csr_u[pu] = d;
    }
}

// ---------------- weight transpose+interleave: W[N][K] -> Wt[k/2][2N] ----------------
struct WtArgs {
    const float* src[10];
    int n[10];
    int k[10];
    int dstN[10];
    int coloff[10];
    int doff[10];
    int blk_off[11];
};

__global__ void wtrans_kernel(WtArgs a, float* __restrict__ dst)
{
    int b = blockIdx.x;
    int m = 0;
    while (b >= a.blk_off[m + 1]) m++;
    int idx = (b - a.blk_off[m]) * 256 + threadIdx.x;
    int N = a.n[m], K = a.k[m];
    if (idx < N * K) {
        int kk = idx / N, nn = idx - kk * N;
        dst[a.doff[m] + (kk >> 1) * 2 * a.dstN[m] + 2 * (a.coloff[m] + nn) + (kk & 1)]
            = a.src[m][nn * K + kk];
    }
}

// ---------------- gather-mean 128-dim, warp/node, unroll-4 ----------------
__global__ __launch_bounds__(256) void gather2_128(
    const float4* __restrict__ featR, const float4* __restrict__ featU,
    const int* __restrict__ off_r, const int* __restrict__ csr_r,
    const int* __restrict__ off_u, const int* __restrict__ csr_u,
    float4* __restrict__ outR, float4* __restrict__ outU)
{
    int warp = (blockIdx.x * blockDim.x + threadIdx.x) >> 5;
    int lane = threadIdx.x & 31;
    const float4* feat;
    const int* off;
    const int* csr;
    float4* outm;
    int node;
    if (warp < NR) {
        feat = featR; off = off_r; csr = csr_r; outm = outR; node = warp;
    } else if (warp < NR + NU) {
        feat = featU; off = off_u; csr = csr_u; outm = outU; node = warp - NR;
    } else return;
    int b = off[node], e = off[node + 1];
    float4 acc = make_float4(0.f, 0.f, 0.f, 0.f);
    int i = b;
    for (; i + 4 <= e; i += 4) {
        int n0 = csr[i], n1 = csr[i + 1], n2 = csr[i + 2], n3 = csr[i + 3];
        float4 v0 = feat[(size_t)n0 * 32 + lane];
        float4 v1 = feat[(size_t)n1 * 32 + lane];
        float4 v2 = feat[(size_t)n2 * 32 + lane];
        float4 v3 = feat[(size_t)n3 * 32 + lane];
        acc.x += v0.x + v1.x + v2.x + v3.x;
        acc.y += v0.y + v1.y + v2.y + v3.y;
        acc.z += v0.z + v1.z + v2.z + v3.z;
        acc.w += v0.w + v1.w + v2.w + v3.w;
    }
    for (; i < e; i++) {
        int nb = csr[i];
        float4 v = feat[(size_t)nb * 32 + lane];
        acc.x += v.x; acc.y += v.y; acc.z += v.z; acc.w += v.w;
    }
    float inv = 1.f / fmaxf((float)(e - b), 1.f);
    acc.x *= inv; acc.y *= inv; acc.z *= inv; acc.w *= inv;
    outm[(size_t)node * 32 + lane] = acc;
}

// ---------------- fused 64-dim gather + bias + root-term ----------------
__global__ __launch_bounds__(256) void gather2_64f(
    const float2* __restrict__ U2, const float2* __restrict__ R2,
    const float* __restrict__ bl_ur, const float* __restrict__ bl_ru,
    const int* __restrict__ off_r, const int* __restrict__ csr_r,
    const int* __restrict__ off_u, const int* __restrict__ csr_u,
    float2* __restrict__ zr, float2* __restrict__ zu)
{
    int warp = (blockIdx.x * blockDim.x + threadIdx.x) >> 5;
    int lane = threadIdx.x & 31;
    const float2* feat;
    const float2* selfp;
    const float2* bl;
    const int* off;
    const int* csr;
    float2* outp;
    int node;
    if (warp < NR) {
        node = warp;
        feat = U2; selfp = R2; bl = (const float2*)bl_ur;
        off = off_r; csr = csr_r; outp = zr;
    } else if (warp < NR + NU) {
        node = warp - NR;
        feat = R2; selfp = U2; bl = (const float2*)bl_ru;
        off = off_u; csr = csr_u; outp = zu;
    } else return;
    int b = off[node], e = off[node + 1];
    float2 acc = make_float2(0.f, 0.f);
    int i = b;
    for (; i + 4 <= e; i += 4) {
        int n0 = csr[i], n1 = csr[i + 1], n2 = csr[i + 2], n3 = csr[i + 3];
        float2 v0 = feat[(size_t)n0 * 64 + lane];
        float2 v1 = feat[(size_t)n1 * 64 + lane];
        float2 v2 = feat[(size_t)n2 * 64 + lane];
        float2 v3 = feat[(size_t)n3 * 64 + lane];
        acc.x += v0.x + v1.x + v2.x + v3.x;
        acc.y += v0.y + v1.y + v2.y + v3.y;
    }
    for (; i < e; i++) {
        int nb = csr[i];
        float2 v = feat[(size_t)nb * 64 + lane];
        acc.x += v.x; acc.y += v.y;
    }
    float inv = 1.f / fmaxf((float)(e - b), 1.f);
    float2 s = selfp[(size_t)node * 64 + 32 + lane];
    float2 bb = bl[lane];
    float2 o;
    o.x = acc.x * inv + bb.x + s.x;
    o.y = acc.y * inv + bb.y + s.y;
    outp[(size_t)node * 32 + lane] = o;
}

// ---------------- mainloop: k-pair packed f32x2, zero packing ----------------
// sW layout: [K/2][2*128], pair (w_k, w_k+1) at float offset kp*256 + 2*col.
// Thread owns cols {2l, 2l+1, 64+2l, 64+2l+1}.
// acc[i][c] f32x2 = (even-k partial, odd-k partial) for col c.
template <int K, bool DUAL>
__device__ __forceinline__ void mm_acc2(
    const float* __restrict__ sA, const float* __restrict__ sX,
    const float* __restrict__ sWl, const float* __restrict__ sWr,
    int r0, int lane, u64 acc[8][4])
{
#pragma unroll 2
    for (int k0 = 0; k0 < K; k0 += 4) {
        const int kp = k0 >> 1;
        // weights for kpair0 (k0,k0+1) and kpair1 (k0+2,k0+3)
        ulonglong2 w0a = *(const ulonglong2*)(sWl + (size_t)kp * 256 + 4 * lane);
        ulonglong2 w0b = *(const ulonglong2*)(sWl + (size_t)kp * 256 + 128 + 4 * lane);
        ulonglong2 w1a = *(const ulonglong2*)(sWl + (size_t)(kp + 1) * 256 + 4 * lane);
        ulonglong2 w1b = *(const ulonglong2*)(sWl + (size_t)(kp + 1) * 256 + 128 + 4 * lane);
        ulonglong2 v0a, v0b, v1a, v1b;
        if (DUAL) {
            v0a = *(const ulonglong2*)(sWr + (size_t)kp * 256 + 4 * lane);
            v0b = *(const ulonglong2*)(sWr + (size_t)kp * 256 + 128 + 4 * lane);
            v1a = *(const ulonglong2*)(sWr + (size_t)(kp + 1) * 256 + 4 * lane);
            v1b = *(const ulonglong2*)(sWr + (size_t)(kp + 1) * 256 + 128 + 4 * lane);
        }
#pragma unroll
        for (int i = 0; i < 8; i++) {
            ulonglong2 av = *(const ulonglong2*)(sA + (size_t)(r0 + i) * K + k0);
            acc[i][0] = fma2(av.x, w0a.x, acc[i][0]);
            acc[i][1] = fma2(av.x, w0a.y, acc[i][1]);
            acc[i][2] = fma2(av.x, w0b.x, acc[i][2]);
            acc[i][3] = fma2(av.x, w0b.y, acc[i][3]);
            acc[i][0] = fma2(av.y, w1a.x, acc[i][0]);
            acc[i][1] = fma2(av.y, w1a.y, acc[i][1]);
            acc[i][2] = fma2(av.y, w1b.x, acc[i][2]);
            acc[i][3] = fma2(av.y, w1b.y, acc[i][3]);
            if (DUAL) {
                ulonglong2 xv = *(const ulonglong2*)(sX + (size_t)(r0 + i) * K + k0);
                acc[i][0] = fma2(xv.x, v0a.x, acc[i][0]);
                acc[i][1] = fma2(xv.x, v0a.y, acc[i][1]);
                acc[i][2] = fma2(xv.x, v0b.x, acc[i][2]);
                acc[i][3] = fma2(xv.x, v0b.y, acc[i][3]);
                acc[i][0] = fma2(xv.y, v1a.x, acc[i][0]);
                acc[i][1] = fma2(xv.y, v1a.y, acc[i][1]);
                acc[i][2] = fma2(xv.y, v1b.x, acc[i][2]);
                acc[i][3] = fma2(xv.y, v1b.y, acc[i][3]);
            }
        }
    }
}

// ---------------- persistent GEMM, N=128 fixed ----------------
// Y = (ADDIN ? ADD : 0) + (HASB ? bl : 0) + A@Wl (+ X@Wr) (+relu)
template <int K, bool DUAL, bool ADDIN, bool HASB, bool RELU>
__global__ __launch_bounds__(256, 1) void gemm2(
    const float* __restrict__ A, const float* __restrict__ X,
    const float* __restrict__ Wlt, const float* __restrict__ Wrt,
    const float* __restrict__ bl, const float* __restrict__ ADDP,
    float* __restrict__ Y, int M)
{
    extern __shared__ float sm[];
    float* sWl = sm;                          // K*128
    float* sWr = sm + (size_t)K * 128;        // K*128 (DUAL)
    float* sA  = sm + (DUAL ? 2 : 1) * (size_t)K * 128;
    float* sX  = sA + 64 * K;

    const int tid = threadIdx.x;

    // stage interleaved weights (flat copy)
    {
        const float4* w4 = (const float4*)Wlt;
        float4* s4 = (float4*)sWl;
        for (int i = tid; i < K * 128 / 4; i += 256) s4[i] = w4[i];
        if (DUAL) {
            const float4* v4 = (const float4*)Wrt;
            float4* t4 = (float4*)sWr;
            for (int i = tid; i < K * 128 / 4; i += 256) t4[i] = v4[i];
        }
    }

    const int lane = tid & 31;
    const int w = tid >> 5;
    const int r0 = w * 8;

    float2 bv01 = make_float2(0.f, 0.f), bv23 = make_float2(0.f, 0.f);
    if (HASB) {
        bv01 = *(const float2*)(bl + 2 * lane);
        bv23 = *(const float2*)(bl + 64 + 2 * lane);
    }

    const int ntiles = (M + 63) >> 6;
    for (int tile = blockIdx.x; tile < ntiles; tile += gridDim.x) {
        const int row0 = tile << 6;
        __syncthreads();
        {
            int lim = min(64, M - row0) * (K / 4);
            const float4* A4 = (const float4*)(A + (size_t)row0 * K);
            float4* sA4 = (float4*)sA;
            const float4* X4 = DUAL ? (const float4*)(X + (size_t)row0 * K) : nullptr;
            float4* sX4 = (float4*)sX;
            for (int i = tid; i < 64 * K / 4; i += 256) {
                float4 v = (i < lim) ? A4[i] : make_float4(0.f, 0.f, 0.f, 0.f);
                sA4[i] = v;
                if (DUAL) {
                    float4 u = (i < lim) ? X4[i] : make_float4(0.f, 0.f, 0.f, 0.f);
                    sX4[i] = u;
                }
            }
        }
        __syncthreads();

        u64 acc[8][4];
#pragma unroll
        for (int i = 0; i < 8; i++)
#pragma unroll
            for (int c = 0; c < 4; c++) acc[i][c] = 0ull;

        mm_acc2<K, DUAL>(sA, sX, sWl, sWr, r0, lane, acc);

#pragma unroll
        for (int i = 0; i < 8; i++) {
            int row = row0 + r0 + i;
            if (row < M) {
                float2 f0 = unpack2(acc[i][0]);
                float2 f1 = unpack2(acc[i][1]);
                float2 f2 = unpack2(acc[i][2]);
                float2 f3 = unpack2(acc[i][3]);
                float2 p = make_float2(f0.x + f0.y + bv01.x, f1.x + f1.y + bv01.y);
                float2 q = make_float2(f2.x + f2.y + bv23.x, f3.x + f3.y + bv23.y);
                if (ADDIN) {
                    float2 a0 = *(const float2*)(ADDP + (size_t)row * 128 + 2 * lane);
                    float2 a1 = *(const float2*)(ADDP + (size_t)row * 128 + 64 + 2 * lane);
                    p.x += a0.x; p.y += a0.y;
                    q.x += a1.x; q.y += a1.y;
                }
                if (RELU) {
                    p.x = fmaxf(p.x, 0.f); p.y = fmaxf(p.y, 0.f);
                    q.x = fmaxf(q.x, 0.f); q.y = fmaxf(q.y, 0.f);
                }
                *(float2*)(Y + (size_t)row * 128 + 2 * lane) = p;
                *(float2*)(Y + (size_t)row * 128 + 64 + 2 * lane) = q;
            }
        }
    }
}

// ---------------- decoder ----------------
__global__ __launch_bounds__(256) void decode_kernel(
    const float2* __restrict__ zu, const float2* __restrict__ zr,
    const int* __restrict__ ls, const int* __restrict__ ld,
    float* __restrict__ out, int L)
{
    int warp = (blockIdx.x * blockDim.x + threadIdx.x) >> 5;
    int lane = threadIdx.x & 31;
    if (warp >= L) return;
    int s = ls[warp], d = ld[warp];
    float2 a = zu[(size_t)s * 32 + lane];
    float2 b = zr[(size_t)d * 32 + lane];
    float dot = a.x * b.x + a.y * b.y;
    float na = a.x * a.x + a.y * a.y;
    float nb = b.x * b.x + b.y * b.y;
#pragma unroll
    for (int o = 16; o; o >>= 1) {
        dot += __shfl_xor_sync(0xffffffffu, dot, o);
        na  += __shfl_xor_sync(0xffffffffu, na, o);
        nb  += __shfl_xor_sync(0xffffffffu, nb, o);
    }
    if (lane == 0)
        out[warp] = dot / (fmaxf(sqrtf(na), 1e-12f) * fmaxf(sqrtf(nb), 1e-12f));
}

// ---------------- host launch ----------------
extern "C" void kernel_launch(void* const* d_in, const int* in_sizes, int n_in,
                              void* d_out, int out_size)
{
    const float* x_user   = (const float*)d_in[0];
    const float* x_recipe = (const float*)d_in[1];
    const int* edge_src   = (const int*)d_in[2];
    const int* edge_dst   = (const int*)d_in[3];
    const int* lbl_src    = (const int*)d_in[4];
    const int* lbl_dst    = (const int*)d_in[5];
    const float* Wu   = (const float*)d_in[6];
    const float* bu   = (const float*)d_in[7];
    const float* Wrec = (const float*)d_in[8];
    const float* brec = (const float*)d_in[9];
    const float* c1_ur_Wl = (const float*)d_in[10];
    const float* c1_ur_bl = (const float*)d_in[11];
    const float* c1_ur_Wr = (const float*)d_in[12];
    const float* c1_ru_Wl = (const float*)d_in[13];
    const float* c1_ru_bl = (const float*)d_in[14];
    const float* c1_ru_Wr = (const float*)d_in[15];
    const float* c2_ur_Wl = (const float*)d_in[16];
    const float* c2_ur_bl = (const float*)d_in[17];
    const float* c2_ur_Wr = (const float*)d_in[18];
    const float* c2_ru_Wl = (const float*)d_in[19];
    const float* c2_ru_bl = (const float*)d_in[20];
    const float* c2_ru_Wr = (const float*)d_in[21];
    float* out = (float*)d_out;

    float *hu, *hr, *p1, *u1, *r1, *mu, *mr, *zu, *zr, *wt;
    int *deg_r, *deg_u, *off_r, *off_u, *cur_r, *cur_u, *csr_r, *csr_u;
    cudaGetSymbolAddress((void**)&hu, g_hu);
    cudaGetSymbolAddress((void**)&hr, g_hr);
    cudaGetSymbolAddress((void**)&p1, g_p1);
    cudaGetSymbolAddress((void**)&u1, g_u1);
    cudaGetSymbolAddress((void**)&r1, g_r1);
    cudaGetSymbolAddress((void**)&mu, g_mean_u);
    cudaGetSymbolAddress((void**)&mr, g_mean_r);
    cudaGetSymbolAddress((void**)&zu, g_zu);
    cudaGetSymbolAddress((void**)&zr, g_zr);
    cudaGetSymbolAddress((void**)&wt, g_wt);
    cudaGetSymbolAddress((void**)&deg_r, g_deg_r);
    cudaGetSymbolAddress((void**)&deg_u, g_deg_u);
    cudaGetSymbolAddress((void**)&off_r, g_off_r);
    cudaGetSymbolAddress((void**)&off_u, g_off_u);
    cudaGetSymbolAddress((void**)&cur_r, g_cur_r);
    cudaGetSymbolAddress((void**)&cur_u, g_cur_u);
    cudaGetSymbolAddress((void**)&csr_r, g_csr_r);
    cudaGetSymbolAddress((void**)&csr_u, g_csr_u);

    static cudaStream_t side = nullptr;
    static cudaEvent_t evF = nullptr, evJ = nullptr;
    if (side == nullptr) {
        cudaStreamCreateWithFlags(&side, cudaStreamNonBlocking);
        cudaEventCreateWithFlags(&evF, cudaEventDisableTiming);
        cudaEventCreateWithFlags(&evJ, cudaEventDisableTiming);
    }

    const int S_P128 = (128 * 128 + 64 * 128) * 4;           // 98304
    const int S_P256 = (256 * 128 + 64 * 256) * 4;           // 196608
    const int S_D128 = (2 * 128 * 128 + 2 * 64 * 128) * 4;   // 196608

    cudaFuncSetAttribute((gemm2<128, false, false, true,  false>),
                         cudaFuncAttributeMaxDynamicSharedMemorySize, S_P128);
    cudaFuncSetAttribute((gemm2<256, false, false, true,  false>),
                         cudaFuncAttributeMaxDynamicSharedMemorySize, S_P256);
    cudaFuncSetAttribute((gemm2<128, false, false, false, false>),
                         cudaFuncAttributeMaxDynamicSharedMemorySize, S_P128);
    cudaFuncSetAttribute((gemm2<128, true,  false, true,  true>),
                         cudaFuncAttributeMaxDynamicSharedMemorySize, S_D128);
    cudaFuncSetAttribute((gemm2<128, false, true,  true,  true>),
                         cudaFuncAttributeMaxDynamicSharedMemorySize, S_P128);

    // ---- fork: CSR on side stream ----
    cudaEventRecord(evF, 0);
    cudaStreamWaitEvent(side, evF, 0);
    zero_deg<<<(NU + 255) / 256, 256, 0, side>>>(deg_u, deg_r);
    count_kernel<<<(NE + 255) / 256, 256, 0, side>>>(edge_src, edge_dst, deg_u, deg_r, NE);
    scan2_kernel<<<2, 1024, 0, side>>>(deg_r, off_r, cur_r, deg_u, off_u, cur_u);
    fill_kernel<<<(NE + 255) / 256, 256, 0, side>>>(edge_src, edge_dst, cur_u, cur_r,
                                                    csr_u, csr_r, NE);
    cudaEventRecord(evJ, side);

    // ---- main: weight transpose+interleave ----
    {
        WtArgs a;
        const float* srcs[10] = {Wu, Wrec, c1_ur_Wl, c1_ur_Wr, c1_ru_Wl, c1_ru_Wr,
                                 c2_ur_Wl, c2_ru_Wr, c2_ru_Wl, c2_ur_Wr};
        int ns[10]   = {128, 128, 128, 128, 128, 128, 64, 64, 64, 64};
        int ks[10]   = {128, 256, 128, 128, 128, 128, 128, 128, 128, 128};
        int dn[10]   = {128, 128, 128, 128, 128, 128, 128, 128, 128, 128};
        int co[10]   = {0, 0, 0, 0, 0, 0, 0, 64, 0, 64};
        int doffs[10] = {WT_WU, WT_WREC, WT_C1URWL, WT_C1URWR, WT_C1RUWL, WT_C1RUWR,
                         WT_U2, WT_U2, WT_R2, WT_R2};
        int boff = 0;
        for (int m = 0; m < 10; m++) {
            a.src[m] = srcs[m]; a.n[m] = ns[m]; a.k[m] = ks[m];
            a.dstN[m] = dn[m]; a.coloff[m] = co[m]; a.doff[m] = doffs[m];
            a.blk_off[m] = boff;
            boff += (ns[m] * ks[m] + 255) / 256;
        }
        a.blk_off[10] = boff;
        wtrans_kernel<<<boff, 256>>>(a, wt);
    }

    // ---- projections ----
    gemm2<128, false, false, true, false><<<296, 256, S_P128>>>(
        x_user, nullptr, wt + WT_WU, nullptr, bu, nullptr, hu, NU);
    gemm2<256, false, false, true, false><<<148, 256, S_P256>>>(
        x_recipe, nullptr, wt + WT_WREC, nullptr, brec, nullptr, hr, NR);
    gemm2<128, false, false, false, false><<<296, 256, S_P128>>>(
        hr, nullptr, wt + WT_C1RUWL, nullptr, nullptr, nullptr, p1, NR);

    // ---- join CSR; conv1 ----
    cudaStreamWaitEvent(0, evJ, 0);
    const int GW = ((NR + NU) * 32 + 255) / 256;
    gather2_128<<<GW, 256>>>((const float4*)hu, (const float4*)p1,
                             off_r, csr_r, off_u, csr_u,
                             (float4*)mr, (float4*)mu);
    gemm2<128, true, false, true, true><<<148, 256, S_D128>>>(
        mr, hr, wt + WT_C1URWL, wt + WT_C1URWR, c1_ur_bl, nullptr, r1, NR);
    gemm2<128, false, true, true, true><<<296, 256, S_P128>>>(
        hu, nullptr, wt + WT_C1RUWR, nullptr, c1_ru_bl, mu, u1, NU);

    // ---- conv2: combined projections then fused gather ----
    gemm2<128, false, false, false, false><<<296, 256, S_P128>>>(
        u1, nullptr, wt + WT_U2, nullptr, nullptr, nullptr, mu, NU);
    gemm2<128, false, false, false, false><<<296, 256, S_P128>>>(
        r1, nullptr, wt + WT_R2, nullptr, nullptr, nullptr, mr, NR);
    gather2_64f<<<GW, 256>>>((const float2*)mu, (const float2*)mr,
                             c2_ur_bl, c2_ru_bl,
                             off_r, csr_r, off_u, csr_u,
                             (float2*)zr, (float2*)zu);

    // ---- decoder ----
    decode_kernel<<<(NL * 32 + 255) / 256, 256>>>(
        (const float2*)zu, (const float2*)zr, lbl_src, lbl_dst, out, NL);
}

// round 7
// speedup vs baseline: 1.2771x; 1.2771x over previous
#include <cuda_runtime.h>
#include <cuda_bf16.h>
#include <math.h>

#define NU 100000
#define NR 50000
#define NE 600000
#define NL 200000
#define HD 128
#define OD 64

typedef unsigned long long u64;

// ---------------- f32x2 packed math ----------------
__device__ __forceinline__ u64 fma2(u64 a, u64 b, u64 c) {
    u64 d;
    asm("fma.rn.f32x2 %0, %1, %2, %3;" : "=l"(d) : "l"(a), "l"(b), "l"(c));
    return d;
}
__device__ __forceinline__ u64 pack2(float x, float y) {
    u64 d; asm("mov.b64 %0, {%1, %2};" : "=l"(d) : "f"(x), "f"(y)); return d;
}
__device__ __forceinline__ float2 unpack2(u64 v) {
    float2 r; asm("mov.b64 {%0, %1}, %2;" : "=f"(r.x), "=f"(r.y) : "l"(v)); return r;
}

// ---------------- scratch ----------------
__device__ __align__(16) float g_hu[(size_t)NU * HD];
__device__ __align__(16) float g_hr[(size_t)NR * HD];
__device__ __align__(16) float g_p1[(size_t)NR * HD];
__device__ __align__(16) float g_u1[(size_t)NU * HD];
__device__ __align__(16) float g_r1[(size_t)NR * HD];
__device__ __align__(16) float g_mean_u[(size_t)NU * HD]; // mu, then U2
__device__ __align__(16) float g_mean_r[(size_t)NR * HD]; // mr, then R2
__device__ __align__(16) float g_zu[(size_t)NU * OD];
__device__ __align__(16) float g_zr[(size_t)NR * OD];
__device__ __align__(16) float g_wt[147456];

__device__ int g_deg_r[NR];
__device__ int g_deg_u[NU];
__device__ int g_off_r[NR + 1];
__device__ int g_off_u[NU + 1];
__device__ int g_cur_r[NR];
__device__ int g_cur_u[NU];
__device__ int g_csr_r[NE];
__device__ int g_csr_u[NE];

#define WT_WU      0
#define WT_WREC    16384
#define WT_C1URWL  49152
#define WT_C1URWR  65536
#define WT_C1RUWL  81920
#define WT_C1RUWR  98304
#define WT_U2      114688   // [128][128]: cols 0-63 c2_ur_Wl^T, 64-127 c2_ru_Wr^T
#define WT_R2      131072   // [128][128]: cols 0-63 c2_ru_Wl^T, 64-127 c2_ur_Wr^T

// ---------------- CSR build ----------------
__global__ void zero_deg(int* __restrict__ deg_u, int* __restrict__ deg_r)
{
    int t = blockIdx.x * blockDim.x + threadIdx.x;
    if (t < NU) deg_u[t] = 0;
    if (t < NR) deg_r[t] = 0;
}

__global__ void count_kernel(const int* __restrict__ es, const int* __restrict__ ed,
                             int* __restrict__ deg_u, int* __restrict__ deg_r, int E)
{
    int t = blockIdx.x * blockDim.x + threadIdx.x;
    if (t < E) {
        atomicAdd(&deg_u[es[t]], 1);
        atomicAdd(&deg_r[ed[t]], 1);
    }
}

__global__ void scan2_kernel(const int* __restrict__ deg_r, int* __restrict__ off_r,
                             int* __restrict__ cur_r,
                             const int* __restrict__ deg_u, int* __restrict__ off_u,
                             int* __restrict__ cur_u)
{
    const int* deg; int* off; int* cur; int n;
    if (blockIdx.x == 0) { deg = deg_r; off = off_r; cur = cur_r; n = NR; }
    else                 { deg = deg_u; off = off_u; cur = cur_u; n = NU; }
    __shared__ int tmp[1024];
    int t = threadIdx.x;
    int chunk = (n + 1023) / 1024;
    int start = min(t * chunk, n);
    int end = min(start + chunk, n);
    int s = 0;
    for (int i = start; i < end; i++) s += deg[i];
    tmp[t] = s;
    __syncthreads();
    for (int d = 1; d < 1024; d <<= 1) {
        int v = (t >= d) ? tmp[t - d] : 0;
        __syncthreads();
        tmp[t] += v;
        __syncthreads();
    }
    int run = (t == 0) ? 0 : tmp[t - 1];
    for (int i = start; i < end; i++) {
        off[i] = run;
        cur[i] = run;
        run += deg[i];
    }
    if (end == n) off[n] = run;
}

__global__ void fill_kernel(const int* __restrict__ es, const int* __restrict__ ed,
                            int* __restrict__ cur_u, int* __restrict__ cur_r,
                            int* __restrict__ csr_u, int* __restrict__ csr_r, int E)
{
    int t = blockIdx.x * blockDim.x + threadIdx.x;
    if (t < E) {
        int s = es[t], d = ed[t];
        int pr = atomicAdd(&cur_r[d], 1);
        csr_r[pr] = s;
        int pu = atomicAdd(&cur_u[s], 1);
        csr_u[pu] = d;
    }
}

// ---------------- weight transpose ----------------
struct WtArgs {
    const float* src[10];
    int n[10];
    int k[10];
    int dstN[10];
    int coloff[10];
    int doff[10];
    int blk_off[11];
};

__global__ void wtrans_kernel(WtArgs a, float* __restrict__ dst)
{
    int b = blockIdx.x;
    int m = 0;
    while (b >= a.blk_off[m + 1]) m++;
    int idx = (b - a.blk_off[m]) * 256 + threadIdx.x;
    int N = a.n[m], K = a.k[m];
    if (idx < N * K) {
        int kk = idx / N, nn = idx - kk * N;
        dst[a.doff[m] + kk * a.dstN[m] + a.coloff[m] + nn] = a.src[m][nn * K + kk];
    }
}

// ---------------- gather-mean 128-dim, warp/node, unroll-4 ----------------
__global__ __launch_bounds__(256) void gather2_128(
    const float4* __restrict__ featR, const float4* __restrict__ featU,
    const int* __restrict__ off_r, const int* __restrict__ csr_r,
    const int* __restrict__ off_u, const int* __restrict__ csr_u,
    float4* __restrict__ outR, float4* __restrict__ outU)
{
    int warp = (blockIdx.x * blockDim.x + threadIdx.x) >> 5;
    int lane = threadIdx.x & 31;
    const float4* feat;
    const int* off;
    const int* csr;
    float4* outm;
    int node;
    if (warp < NR) {
        feat = featR; off = off_r; csr = csr_r; outm = outR; node = warp;
    } else if (warp < NR + NU) {
        feat = featU; off = off_u; csr = csr_u; outm = outU; node = warp - NR;
    } else return;
    int b = off[node], e = off[node + 1];
    float4 acc = make_float4(0.f, 0.f, 0.f, 0.f);
    int i = b;
    for (; i + 4 <= e; i += 4) {
        int n0 = csr[i], n1 = csr[i + 1], n2 = csr[i + 2], n3 = csr[i + 3];
        float4 v0 = feat[(size_t)n0 * 32 + lane];
        float4 v1 = feat[(size_t)n1 * 32 + lane];
        float4 v2 = feat[(size_t)n2 * 32 + lane];
        float4 v3 = feat[(size_t)n3 * 32 + lane];
        acc.x += v0.x + v1.x + v2.x + v3.x;
        acc.y += v0.y + v1.y + v2.y + v3.y;
        acc.z += v0.z + v1.z + v2.z + v3.z;
        acc.w += v0.w + v1.w + v2.w + v3.w;
    }
    for (; i < e; i++) {
        int nb = csr[i];
        float4 v = feat[(size_t)nb * 32 + lane];
        acc.x += v.x; acc.y += v.y; acc.z += v.z; acc.w += v.w;
    }
    float inv = 1.f / fmaxf((float)(e - b), 1.f);
    acc.x *= inv; acc.y *= inv; acc.z *= inv; acc.w *= inv;
    outm[(size_t)node * 32 + lane] = acc;
}

// ---------------- fused 64-dim gather + bias + root + NORMALIZE ----------------
// Produces already-L2-normalized z rows, so the decoder only needs a dot.
__global__ __launch_bounds__(256) void gather2_64f(
    const float2* __restrict__ U2, const float2* __restrict__ R2,
    const float* __restrict__ bl_ur, const float* __restrict__ bl_ru,
    const int* __restrict__ off_r, const int* __restrict__ csr_r,
    const int* __restrict__ off_u, const int* __restrict__ csr_u,
    float2* __restrict__ zr, float2* __restrict__ zu)
{
    int warp = (blockIdx.x * blockDim.x + threadIdx.x) >> 5;
    int lane = threadIdx.x & 31;
    const float2* feat;
    const float2* selfp;
    const float2* bl;
    const int* off;
    const int* csr;
    float2* outp;
    int node;
    if (warp < NR) {
        node = warp;
        feat = U2; selfp = R2; bl = (const float2*)bl_ur;
        off = off_r; csr = csr_r; outp = zr;
    } else if (warp < NR + NU) {
        node = warp - NR;
        feat = R2; selfp = U2; bl = (const float2*)bl_ru;
        off = off_u; csr = csr_u; outp = zu;
    } else return;
    int b = off[node], e = off[node + 1];
    float2 acc = make_float2(0.f, 0.f);
    int i = b;
    for (; i + 4 <= e; i += 4) {
        int n0 = csr[i], n1 = csr[i + 1], n2 = csr[i + 2], n3 = csr[i + 3];
        float2 v0 = feat[(size_t)n0 * 64 + lane];
        float2 v1 = feat[(size_t)n1 * 64 + lane];
        float2 v2 = feat[(size_t)n2 * 64 + lane];
        float2 v3 = feat[(size_t)n3 * 64 + lane];
        acc.x += v0.x + v1.x + v2.x + v3.x;
        acc.y += v0.y + v1.y + v2.y + v3.y;
    }
    for (; i < e; i++) {
        int nb = csr[i];
        float2 v = feat[(size_t)nb * 64 + lane];
        acc.x += v.x; acc.y += v.y;
    }
    float inv = 1.f / fmaxf((float)(e - b), 1.f);
    float2 s = selfp[(size_t)node * 64 + 32 + lane];
    float2 bb = bl[lane];
    float2 o;
    o.x = acc.x * inv + bb.x + s.x;
    o.y = acc.y * inv + bb.y + s.y;
    // L2-normalize the 64-d row held across the warp
    float nsum = o.x * o.x + o.y * o.y;
#pragma unroll
    for (int ofs = 16; ofs; ofs >>= 1)
        nsum += __shfl_xor_sync(0xffffffffu, nsum, ofs);
    float innorm = 1.f / fmaxf(sqrtf(nsum), 1e-12f);
    o.x *= innorm; o.y *= innorm;
    outp[(size_t)node * 32 + lane] = o;
}

// ---------------- shared mainloop (style A): acc += sA@sWl (+ sX@sWr) ----------------
template <int N, int K, bool DUAL>
__device__ __forceinline__ void mm_acc(
    const float* __restrict__ sA, const float* __restrict__ sX,
    const float* __restrict__ sWl, const float* __restrict__ sWr,
    int r0, int colbase, u64 acc[8][N / 64])
{
    constexpr int CPT = N / 32;
    constexpr int PAIRS = CPT / 2;
#pragma unroll 2
    for (int k0 = 0; k0 < K; k0 += 4) {
        float4 a4[8], x4[8];
#pragma unroll
        for (int i = 0; i < 8; i++) {
            a4[i] = *(const float4*)&sA[(r0 + i) * K + k0];
            if (DUAL) x4[i] = *(const float4*)&sX[(r0 + i) * K + k0];
        }
#pragma unroll
        for (int kk = 0; kk < 4; kk++) {
            u64 wl[PAIRS], wr[PAIRS];
            const float* wlp = &sWl[(k0 + kk) * N + colbase];
            if (CPT == 4) {
                float4 v = *(const float4*)wlp;
                wl[0] = pack2(v.x, v.y);
                if (PAIRS > 1) wl[1] = pack2(v.z, v.w);
            } else {
                float2 v = *(const float2*)wlp;
                wl[0] = pack2(v.x, v.y);
            }
            if (DUAL) {
                const float* wrp = &sWr[(k0 + kk) * N + colbase];
                if (CPT == 4) {
                    float4 v = *(const float4*)wrp;
                    wr[0] = pack2(v.x, v.y);
                    if (PAIRS > 1) wr[1] = pack2(v.z, v.w);
                } else {
                    float2 v = *(const float2*)wrp;
                    wr[0] = pack2(v.x, v.y);
                }
            }
#pragma unroll
            for (int i = 0; i < 8; i++) {
                float as = (kk == 0) ? a4[i].x : (kk == 1) ? a4[i].y :
                           (kk == 2) ? a4[i].z : a4[i].w;
                u64 a2 = pack2(as, as);
#pragma unroll
                for (int p = 0; p < PAIRS; p++) acc[i][p] = fma2(a2, wl[p], acc[i][p]);
                if (DUAL) {
                    float xs = (kk == 0) ? x4[i].x : (kk == 1) ? x4[i].y :
                               (kk == 2) ? x4[i].z : x4[i].w;
                    u64 x2 = pack2(xs, xs);
#pragma unroll
                    for (int p = 0; p < PAIRS; p++) acc[i][p] = fma2(x2, wr[p], acc[i][p]);
                }
            }
        }
    }
}

// ---------------- persistent GEMM ----------------
template <int N, int K, bool DUAL, bool ADDIN, bool HASB, bool RELU>
__global__ __launch_bounds__(256) void gemm_k(
    const float* __restrict__ A, const float* __restrict__ X,
    const float* __restrict__ Wlt, const float* __restrict__ Wrt,
    const float* __restrict__ bl, const float* __restrict__ ADDP,
    float* __restrict__ Y, int M)
{
    constexpr int CPT = N / 32;
    constexpr int PAIRS = CPT / 2;
    extern __shared__ float sm[];
    float* sWl = sm;
    float* sWr = sm + K * N;
    float* sA  = sm + (DUAL ? 2 : 1) * K * N;
    float* sX  = sA + 64 * K;

    const int tid = threadIdx.x;

    {
        const float4* w4 = (const float4*)Wlt;
        float4* s4 = (float4*)sWl;
        for (int i = tid; i < K * N / 4; i += 256) s4[i] = w4[i];
        if (DUAL) {
            const float4* v4 = (const float4*)Wrt;
            float4* t4 = (float4*)sWr;
            for (int i = tid; i < K * N / 4; i += 256) t4[i] = v4[i];
        }
    }

    const int lane = tid & 31;
    const int w = tid >> 5;
    const int r0 = w * 8;
    const int colbase = lane * CPT;

    float bv[CPT];
#pragma unroll
    for (int j = 0; j < CPT; j++) bv[j] = HASB ? bl[colbase + j] : 0.f;

    const int ntiles = (M + 63) >> 6;
    for (int tile = blockIdx.x; tile < ntiles; tile += gridDim.x) {
        const int row0 = tile << 6;
        __syncthreads();
        {
            int lim = min(64, M - row0) * (K / 4);
            const float4* A4 = (const float4*)(A + (size_t)row0 * K);
            float4* sA4 = (float4*)sA;
            const float4* X4 = DUAL ? (const float4*)(X + (size_t)row0 * K) : nullptr;
            float4* sX4 = (float4*)sX;
            for (int i = tid; i < 64 * K / 4; i += 256) {
                float4 v = (i < lim) ? A4[i] : make_float4(0.f, 0.f, 0.f, 0.f);
                sA4[i] = v;
                if (DUAL) {
                    float4 u = (i < lim) ? X4[i] : make_float4(0.f, 0.f, 0.f, 0.f);
                    sX4[i] = u;
                }
            }
        }
        __syncthreads();

        u64 acc[8][PAIRS];
#pragma unroll
        for (int i = 0; i < 8; i++)
#pragma unroll
            for (int p = 0; p < PAIRS; p++) acc[i][p] = 0ull;

        mm_acc<N, K, DUAL>(sA, sX, sWl, sWr, r0, colbase, acc);

#pragma unroll
        for (int i = 0; i < 8; i++) {
            int row = row0 + r0 + i;
            if (row < M) {
                float o[CPT];
#pragma unroll
                for (int p = 0; p < PAIRS; p++) {
                    float2 v = unpack2(acc[i][p]);
                    o[2 * p] = v.x + bv[2 * p];
                    o[2 * p + 1] = v.y + bv[2 * p + 1];
                }
                if (ADDIN) {
                    const float* ap = &ADDP[(size_t)row * N + colbase];
                    if (CPT == 4) {
                        float4 v = *(const float4*)ap;
                        o[0] += v.x; o[1] += v.y; o[2] += v.z; o[3] += v.w;
                    } else {
                        float2 v = *(const float2*)ap;
                        o[0] += v.x; o[1] += v.y;
                    }
                }
                if (RELU) {
#pragma unroll
                    for (int j = 0; j < CPT; j++) o[j] = fmaxf(o[j], 0.f);
                }
                float* yp = &Y[(size_t)row * N + colbase];
                if (CPT == 4) *(float4*)yp = make_float4(o[0], o[1], o[2], o[3]);
                else          *(float2*)yp = make_float2(o[0], o[1]);
            }
        }
    }
}

// ---------------- decoder: dot of pre-normalized rows ----------------
__global__ __launch_bounds__(256) void decode_kernel(
    const float2* __restrict__ zu, const float2* __restrict__ zr,
    const int* __restrict__ ls, const int* __restrict__ ld,
    float* __restrict__ out, int L)
{
    int warp = (blockIdx.x * blockDim.x + threadIdx.x) >> 5;
    int lane = threadIdx.x & 31;
    if (warp >= L) return;
    int s = ls[warp], d = ld[warp];
    float2 a = zu[(size_t)s * 32 + lane];
    float2 b = zr[(size_t)d * 32 + lane];
    float dot = a.x * b.x + a.y * b.y;
#pragma unroll
    for (int o = 16; o; o >>= 1)
        dot += __shfl_xor_sync(0xffffffffu, dot, o);
    if (lane == 0)
        out[warp] = dot;
}

// ---------------- host launch ----------------
extern "C" void kernel_launch(void* const* d_in, const int* in_sizes, int n_in,
                              void* d_out, int out_size)
{
    const float* x_user   = (const float*)d_in[0];
    const float* x_recipe = (const float*)d_in[1];
    const int* edge_src   = (const int*)d_in[2];
    const int* edge_dst   = (const int*)d_in[3];
    const int* lbl_src    = (const int*)d_in[4];
    const int* lbl_dst    = (const int*)d_in[5];
    const float* Wu   = (const float*)d_in[6];
    const float* bu   = (const float*)d_in[7];
    const float* Wrec = (const float*)d_in[8];
    const float* brec = (const float*)d_in[9];
    const float* c1_ur_Wl = (const float*)d_in[10];
    const float* c1_ur_bl = (const float*)d_in[11];
    const float* c1_ur_Wr = (const float*)d_in[12];
    const float* c1_ru_Wl = (const float*)d_in[13];
    const float* c1_ru_bl = (const float*)d_in[14];
    const float* c1_ru_Wr = (const float*)d_in[15];
    const float* c2_ur_Wl = (const float*)d_in[16];
    const float* c2_ur_bl = (const float*)d_in[17];
    const float* c2_ur_Wr = (const float*)d_in[18];
    const float* c2_ru_Wl = (const float*)d_in[19];
    const float* c2_ru_bl = (const float*)d_in[20];
    const float* c2_ru_Wr = (const float*)d_in[21];
    float* out = (float*)d_out;

    float *hu, *hr, *p1, *u1, *r1, *mu, *mr, *zu, *zr, *wt;
    int *deg_r, *deg_u, *off_r, *off_u, *cur_r, *cur_u, *csr_r, *csr_u;
    cudaGetSymbolAddress((void**)&hu, g_hu);
    cudaGetSymbolAddress((void**)&hr, g_hr);
    cudaGetSymbolAddress((void**)&p1, g_p1);
    cudaGetSymbolAddress((void**)&u1, g_u1);
    cudaGetSymbolAddress((void**)&r1, g_r1);
    cudaGetSymbolAddress((void**)&mu, g_mean_u);
    cudaGetSymbolAddress((void**)&mr, g_mean_r);
    cudaGetSymbolAddress((void**)&zu, g_zu);
    cudaGetSymbolAddress((void**)&zr, g_zr);
    cudaGetSymbolAddress((void**)&wt, g_wt);
    cudaGetSymbolAddress((void**)&deg_r, g_deg_r);
    cudaGetSymbolAddress((void**)&deg_u, g_deg_u);
    cudaGetSymbolAddress((void**)&off_r, g_off_r);
    cudaGetSymbolAddress((void**)&off_u, g_off_u);
    cudaGetSymbolAddress((void**)&cur_r, g_cur_r);
    cudaGetSymbolAddress((void**)&cur_u, g_cur_u);
    cudaGetSymbolAddress((void**)&csr_r, g_csr_r);
    cudaGetSymbolAddress((void**)&csr_u, g_csr_u);

    static cudaStream_t side = nullptr, s2 = nullptr;
    static cudaEvent_t evF = nullptr, evJ = nullptr, evG = nullptr, evA = nullptr;
    if (side == nullptr) {
        cudaStreamCreateWithFlags(&side, cudaStreamNonBlocking);
        cudaStreamCreateWithFlags(&s2, cudaStreamNonBlocking);
        cudaEventCreateWithFlags(&evF, cudaEventDisableTiming);
        cudaEventCreateWithFlags(&evJ, cudaEventDisableTiming);
        cudaEventCreateWithFlags(&evG, cudaEventDisableTiming);
        cudaEventCreateWithFlags(&evA, cudaEventDisableTiming);
    }

    const int S_P128 = (128 * 128 + 64 * 128) * 4;           // 98304
    const int S_P256 = (256 * 128 + 64 * 256) * 4;           // 196608
    const int S_D128 = (2 * 128 * 128 + 2 * 64 * 128) * 4;   // 196608

    cudaFuncSetAttribute((gemm_k<128, 128, false, false, true,  false>),
                         cudaFuncAttributeMaxDynamicSharedMemorySize, S_P128);
    cudaFuncSetAttribute((gemm_k<128, 256, false, false, true,  false>),
                         cudaFuncAttributeMaxDynamicSharedMemorySize, S_P256);
    cudaFuncSetAttribute((gemm_k<128, 128, false, false, false, false>),
                         cudaFuncAttributeMaxDynamicSharedMemorySize, S_P128);
    cudaFuncSetAttribute((gemm_k<128, 128, true,  false, true,  true>),
                         cudaFuncAttributeMaxDynamicSharedMemorySize, S_D128);
    cudaFuncSetAttribute((gemm_k<128, 128, false, true,  true,  true>),
                         cudaFuncAttributeMaxDynamicSharedMemorySize, S_P128);

    // ---- fork: CSR on side stream ----
    cudaEventRecord(evF, 0);
    cudaStreamWaitEvent(side, evF, 0);
    zero_deg<<<(NU + 255) / 256, 256, 0, side>>>(deg_u, deg_r);
    count_kernel<<<(NE + 255) / 256, 256, 0, side>>>(edge_src, edge_dst, deg_u, deg_r, NE);
    scan2_kernel<<<2, 1024, 0, side>>>(deg_r, off_r, cur_r, deg_u, off_u, cur_u);
    fill_kernel<<<(NE + 255) / 256, 256, 0, side>>>(edge_src, edge_dst, cur_u, cur_r,
                                                    csr_u, csr_r, NE);
    cudaEventRecord(evJ, side);

    // ---- main: weight transpose + projections ----
    {
        WtArgs a;
        const float* srcs[10] = {Wu, Wrec, c1_ur_Wl, c1_ur_Wr, c1_ru_Wl, c1_ru_Wr,
                                 c2_ur_Wl, c2_ru_Wr, c2_ru_Wl, c2_ur_Wr};
        int ns[10]   = {128, 128, 128, 128, 128, 128, 64, 64, 64, 64};
        int ks[10]   = {128, 256, 128, 128, 128, 128, 128, 128, 128, 128};
        int dn[10]   = {128, 128, 128, 128, 128, 128, 128, 128, 128, 128};
        int co[10]   = {0, 0, 0, 0, 0, 0, 0, 64, 0, 64};
        int doffs[10] = {WT_WU, WT_WREC, WT_C1URWL, WT_C1URWR, WT_C1RUWL, WT_C1RUWR,
                         WT_U2, WT_U2, WT_R2, WT_R2};
        int boff = 0;
        for (int m = 0; m < 10; m++) {
            a.src[m] = srcs[m]; a.n[m] = ns[m]; a.k[m] = ks[m];
            a.dstN[m] = dn[m]; a.coloff[m] = co[m]; a.doff[m] = doffs[m];
            a.blk_off[m] = boff;
            boff += (ns[m] * ks[m] + 255) / 256;
        }
        a.blk_off[10] = boff;
        wtrans_kernel<<<boff, 256>>>(a, wt);
    }

    gemm_k<128, 128, false, false, true, false><<<296, 256, S_P128>>>(
        x_user, nullptr, wt + WT_WU, nullptr, bu, nullptr, hu, NU);
    gemm_k<128, 256, false, false, true, false><<<148, 256, S_P256>>>(
        x_recipe, nullptr, wt + WT_WREC, nullptr, brec, nullptr, hr, NR);
    gemm_k<128, 128, false, false, false, false><<<296, 256, S_P128>>>(
        hr, nullptr, wt + WT_C1RUWL, nullptr, nullptr, nullptr, p1, NR);

    // ---- join CSR; conv1 gather ----
    cudaStreamWaitEvent(0, evJ, 0);
    const int GW = ((NR + NU) * 32 + 255) / 256;
    gather2_128<<<GW, 256>>>((const float4*)hu, (const float4*)p1,
                             off_r, csr_r, off_u, csr_u,
                             (float4*)mr, (float4*)mu);
    cudaEventRecord(evG, 0);

    // ---- chain A on s2: r1 (dual) -> R2 ----
    cudaStreamWaitEvent(s2, evG, 0);
    gemm_k<128, 128, true, false, true, true><<<148, 256, S_D128, s2>>>(
        mr, hr, wt + WT_C1URWL, wt + WT_C1URWR, c1_ur_bl, nullptr, r1, NR);
    gemm_k<128, 128, false, false, false, false><<<296, 256, S_P128, s2>>>(
        r1, nullptr, wt + WT_R2, nullptr, nullptr, nullptr, mr, NR);
    cudaEventRecord(evA, s2);

    // ---- chain B on main: u1 (ADDIN mu) -> U2 ----
    gemm_k<128, 128, false, true, true, true><<<296, 256, S_P128>>>(
        hu, nullptr, wt + WT_C1RUWR, nullptr, c1_ru_bl, mu, u1, NU);
    gemm_k<128, 128, false, false, false, false><<<296, 256, S_P128>>>(
        u1, nullptr, wt + WT_U2, nullptr, nullptr, nullptr, mu, NU);

    // ---- join; fused conv2 gather (normalized outputs) ----
    cudaStreamWaitEvent(0, evA, 0);
    gather2_64f<<<GW, 256>>>((const float2*)mu, (const float2*)mr,
                             c2_ur_bl, c2_ru_bl,
                             off_r, csr_r, off_u, csr_u,
                             (float2*)zr, (float2*)zu);

    // ---- decoder ----
    decode_kernel<<<(NL * 32 + 255) / 256, 256>>>(
        (const float2*)zu, (const float2*)zr, lbl_src, lbl_dst, out, NL);
}

// round 8
// speedup vs baseline: 1.3823x; 1.0824x over previous
#include <cuda_runtime.h>
#include <cuda_bf16.h>
#include <mma.h>
#include <math.h>

using namespace nvcuda;

#define NU 100000
#define NR 50000
#define NE 600000
#define NL 200000
#define HD 128
#define OD 64

typedef unsigned long long u64;

// ---------------- f32x2 packed math ----------------
__device__ __forceinline__ u64 fma2(u64 a, u64 b, u64 c) {
    u64 d;
    asm("fma.rn.f32x2 %0, %1, %2, %3;" : "=l"(d) : "l"(a), "l"(b), "l"(c));
    return d;
}
__device__ __forceinline__ u64 pack2(float x, float y) {
    u64 d; asm("mov.b64 %0, {%1, %2};" : "=l"(d) : "f"(x), "f"(y)); return d;
}
__device__ __forceinline__ float2 unpack2(u64 v) {
    float2 r; asm("mov.b64 {%0, %1}, %2;" : "=f"(r.x), "=f"(r.y) : "l"(v)); return r;
}

// ---------------- scratch ----------------
__device__ __align__(16) float g_hu[(size_t)NU * HD];
__device__ __align__(16) float g_hr[(size_t)NR * HD];
__device__ __align__(16) float g_p1[(size_t)NR * HD];
__device__ __align__(16) float g_u1[(size_t)NU * HD];
__device__ __align__(16) float g_r1[(size_t)NR * HD];
__device__ __align__(16) float g_mean_u[(size_t)NU * HD]; // mu, then U2
__device__ __align__(16) float g_mean_r[(size_t)NR * HD]; // mr, then R2
__device__ __align__(16) float g_zu[(size_t)NU * OD];
__device__ __align__(16) float g_zr[(size_t)NR * OD];
__device__ __align__(16) float g_wt[147456];

// bf16 split weights for wmma projections: layouts [N][K+8]
__device__ __align__(16) __nv_bfloat16 g_wbh[68608];
__device__ __align__(16) __nv_bfloat16 g_wbl[68608];
#define WB_WU   0        // Wu   [128][136]
#define WB_WREC 17408    // Wrec [128][264]
#define WB_P1   51200    // c1_ru_Wl [128][136]

__device__ int g_deg_r[NR];
__device__ int g_deg_u[NU];
__device__ int g_off_r[NR + 1];
__device__ int g_off_u[NU + 1];
__device__ int g_cur_r[NR];
__device__ int g_cur_u[NU];
__device__ int g_csr_r[NE];
__device__ int g_csr_u[NE];

#define WT_C1URWL  49152
#define WT_C1URWR  65536
#define WT_C1RUWR  98304
#define WT_U2      114688   // [128][128]: cols 0-63 c2_ur_Wl^T, 64-127 c2_ru_Wr^T
#define WT_R2      131072   // [128][128]: cols 0-63 c2_ru_Wl^T, 64-127 c2_ur_Wr^T

// ---------------- CSR build ----------------
__global__ void zero_deg(int* __restrict__ deg_u, int* __restrict__ deg_r)
{
    int t = blockIdx.x * blockDim.x + threadIdx.x;
    if (t < NU) deg_u[t] = 0;
    if (t < NR) deg_r[t] = 0;
}

__global__ void count_kernel(const int* __restrict__ es, const int* __restrict__ ed,
                             int* __restrict__ deg_u, int* __restrict__ deg_r, int E)
{
    int t = blockIdx.x * blockDim.x + threadIdx.x;
    if (t < E) {
        atomicAdd(&deg_u[es[t]], 1);
        atomicAdd(&deg_r[ed[t]], 1);
    }
}

__global__ void scan2_kernel(const int* __restrict__ deg_r, int* __restrict__ off_r,
                             int* __restrict__ cur_r,
                             const int* __restrict__ deg_u, int* __restrict__ off_u,
                             int* __restrict__ cur_u)
{
    const int* deg; int* off; int* cur; int n;
    if (blockIdx.x == 0) { deg = deg_r; off = off_r; cur = cur_r; n = NR; }
    else                 { deg = deg_u; off = off_u; cur = cur_u; n = NU; }
    __shared__ int tmp[1024];
    int t = threadIdx.x;
    int chunk = (n + 1023) / 1024;
    int start = min(t * chunk, n);
    int end = min(start + chunk, n);
    int s = 0;
    for (int i = start; i < end; i++) s += deg[i];
    tmp[t] = s;
    __syncthreads();
    for (int d = 1; d < 1024; d <<= 1) {
        int v = (t >= d) ? tmp[t - d] : 0;
        __syncthreads();
        tmp[t] += v;
        __syncthreads();
    }
    int run = (t == 0) ? 0 : tmp[t - 1];
    for (int i = start; i < end; i++) {
        off[i] = run;
        cur[i] = run;
        run += deg[i];
    }
    if (end == n) off[n] = run;
}

__global__ void fill_kernel(const int* __restrict__ es, const int* __restrict__ ed,
                            int* __restrict__ cur_u, int* __restrict__ cur_r,
                            int* __restrict__ csr_u, int* __restrict__ csr_r, int E)
{
    int t = blockIdx.x * blockDim.x + threadIdx.x;
    if (t < E) {
        int s = es[t], d = ed[t];
        int pr = atomicAdd(&cur_r[d], 1);
        csr_r[pr] = s;
        int pu = atomicAdd(&cur_u[s], 1);
        csr_u[pu] = d;
    }
}

// ---------------- fp32 weight transpose (conv GEMMs) ----------------
struct WtArgs {
    const float* src[7];
    int n[7];
    int k[7];
    int dstN[7];
    int coloff[7];
    int doff[7];
    int blk_off[8];
};

__global__ void wtrans_kernel(WtArgs a, float* __restrict__ dst)
{
    int b = blockIdx.x;
    int m = 0;
    while (b >= a.blk_off[m + 1]) m++;
    int idx = (b - a.blk_off[m]) * 256 + threadIdx.x;
    int N = a.n[m], K = a.k[m];
    if (idx < N * K) {
        int kk = idx / N, nn = idx - kk * N;
        dst[a.doff[m] + kk * a.dstN[m] + a.coloff[m] + nn] = a.src[m][nn * K + kk];
    }
}

// ---------------- bf16 split weight conversion (wmma projections) ----------------
struct WbArgs {
    const float* src[3];
    int n[3];
    int k[3];
    int kp[3];
    int doff[3];
    int blk_off[4];
};

__global__ void wconv_kernel(WbArgs a, __nv_bfloat16* __restrict__ hi,
                             __nv_bfloat16* __restrict__ lo)
{
    int b = blockIdx.x;
    int m = 0;
    while (b >= a.blk_off[m + 1]) m++;
    int idx = (b - a.blk_off[m]) * 256 + threadIdx.x;
    int N = a.n[m], K = a.k[m], KP = a.kp[m];
    if (idx < N * KP) {
        int nn = idx / KP, kk = idx - nn * KP;
        float v = (kk < K) ? a.src[m][nn * K + kk] : 0.f;
        __nv_bfloat16 h = __float2bfloat16(v);
        float r = v - __bfloat162float(h);
        hi[a.doff[m] + idx] = h;
        lo[a.doff[m] + idx] = __float2bfloat16(r);
    }
}

// ---------------- wmma split-bf16 GEMM: Y[M,128] = A[M,K] @ W[128,K]^T (+bl) ----------------
// W given as split bf16 hi/lo in [128][K+8] row-major (= col-major B fragment view).
template <int K, bool HASB>
__global__ __launch_bounds__(256) void gemm_wmma(
    const float* __restrict__ A,
    const __nv_bfloat16* __restrict__ Whi, const __nv_bfloat16* __restrict__ Wlo,
    const float* __restrict__ bl, float* __restrict__ Y, int M)
{
    constexpr int KP = K + 8;
    extern __shared__ __nv_bfloat16 smemb[];
    __nv_bfloat16* sWhi = smemb;                 // 128*KP
    __nv_bfloat16* sWlo = sWhi + 128 * KP;       // 128*KP
    __nv_bfloat16* sAhi = sWlo + 128 * KP;       // 64*KP
    __nv_bfloat16* sAlo = sAhi + 64 * KP;        // 64*KP
    float* sOut = (float*)sAhi;                  // aliased after mainloop (64*KP*4B >= 32KB)

    const int tid = threadIdx.x;

    // stage weights once (flat uint4 copy; rows are 16B multiples)
    {
        const uint4* src = (const uint4*)Whi;
        uint4* dst = (uint4*)sWhi;
        for (int i = tid; i < 128 * KP / 8; i += 256) dst[i] = src[i];
        const uint4* src2 = (const uint4*)Wlo;
        uint4* dst2 = (uint4*)sWlo;
        for (int i = tid; i < 128 * KP / 8; i += 256) dst2[i] = src2[i];
    }

    const int w = tid >> 5;
    const int mrow0 = (w >> 2) * 32;   // 2 warps in M
    const int ncol0 = (w & 3) * 32;    // 4 warps in N

    const int ntiles = (M + 63) >> 6;
    for (int tile = blockIdx.x; tile < ntiles; tile += gridDim.x) {
        const int row0 = tile << 6;
        __syncthreads();  // protect sA/sOut from previous iteration readers
        // stage A with on-the-fly bf16 split
        {
            int rows = min(64, M - row0);
            for (int i = tid; i < 64 * (K / 4); i += 256) {
                int r = i / (K / 4), kq = i - r * (K / 4);
                float4 v = make_float4(0.f, 0.f, 0.f, 0.f);
                if (r < rows) v = *(const float4*)(A + (size_t)(row0 + r) * K + 4 * kq);
                float vv[4] = {v.x, v.y, v.z, v.w};
                unsigned ph0 = 0, ph1 = 0, pl0 = 0, pl1 = 0;
#pragma unroll
                for (int q = 0; q < 2; q++) {
                    __nv_bfloat16 h = __float2bfloat16(vv[q]);
                    __nv_bfloat16 l = __float2bfloat16(vv[q] - __bfloat162float(h));
                    ph0 |= (unsigned)__bfloat16_as_ushort(h) << (16 * q);
                    pl0 |= (unsigned)__bfloat16_as_ushort(l) << (16 * q);
                }
#pragma unroll
                for (int q = 0; q < 2; q++) {
                    __nv_bfloat16 h = __float2bfloat16(vv[2 + q]);
                    __nv_bfloat16 l = __float2bfloat16(vv[2 + q] - __bfloat162float(h));
                    ph1 |= (unsigned)__bfloat16_as_ushort(h) << (16 * q);
                    pl1 |= (unsigned)__bfloat16_as_ushort(l) << (16 * q);
                }
                *(uint2*)&sAhi[r * KP + 4 * kq] = make_uint2(ph0, ph1);
                *(uint2*)&sAlo[r * KP + 4 * kq] = make_uint2(pl0, pl1);
            }
        }
        __syncthreads();

        wmma::fragment<wmma::accumulator, 16, 16, 16, float> acc[2][2];
#pragma unroll
        for (int i = 0; i < 2; i++)
#pragma unroll
            for (int j = 0; j < 2; j++) wmma::fill_fragment(acc[i][j], 0.f);

        for (int k0 = 0; k0 < K; k0 += 16) {
            wmma::fragment<wmma::matrix_a, 16, 16, 16, __nv_bfloat16, wmma::row_major> ahi[2], alo[2];
            wmma::fragment<wmma::matrix_b, 16, 16, 16, __nv_bfloat16, wmma::col_major> bhi[2], blo[2];
#pragma unroll
            for (int i = 0; i < 2; i++) {
                wmma::load_matrix_sync(ahi[i], sAhi + (mrow0 + 16 * i) * KP + k0, KP);
                wmma::load_matrix_sync(alo[i], sAlo + (mrow0 + 16 * i) * KP + k0, KP);
            }
#pragma unroll
            for (int j = 0; j < 2; j++) {
                wmma::load_matrix_sync(bhi[j], sWhi + (ncol0 + 16 * j) * KP + k0, KP);
                wmma::load_matrix_sync(blo[j], sWlo + (ncol0 + 16 * j) * KP + k0, KP);
            }
#pragma unroll
            for (int i = 0; i < 2; i++)
#pragma unroll
                for (int j = 0; j < 2; j++) {
                    wmma::mma_sync(acc[i][j], ahi[i], bhi[j], acc[i][j]);
                    wmma::mma_sync(acc[i][j], ahi[i], blo[j], acc[i][j]);
                    wmma::mma_sync(acc[i][j], alo[i], bhi[j], acc[i][j]);
                }
        }

        __syncthreads();  // all fragment loads done before sOut overwrites sA
#pragma unroll
        for (int i = 0; i < 2; i++)
#pragma unroll
            for (int j = 0; j < 2; j++)
                wmma::store_matrix_sync(sOut + (mrow0 + 16 * i) * 128 + ncol0 + 16 * j,
                                        acc[i][j], 128, wmma::mem_row_major);
        __syncthreads();

        {
            int rows = min(64, M - row0);
            for (int i = tid; i < 64 * 32; i += 256) {
                int r = i >> 5, c4 = i & 31;
                if (r < rows) {
                    float4 v = ((const float4*)sOut)[i];
                    if (HASB) {
                        float4 b4 = *(const float4*)(bl + 4 * c4);
                        v.x += b4.x; v.y += b4.y; v.z += b4.z; v.w += b4.w;
                    }
                    *(float4*)(Y + (size_t)(row0 + r) * 128 + 4 * c4) = v;
                }
            }
        }
    }
}

// ---------------- gather-mean 128-dim, warp/node, unroll-4 ----------------
__global__ __launch_bounds__(256) void gather2_128(
    const float4* __restrict__ featR, const float4* __restrict__ featU,
    const int* __restrict__ off_r, const int* __restrict__ csr_r,
    const int* __restrict__ off_u, const int* __restrict__ csr_u,
    float4* __restrict__ outR, float4* __restrict__ outU)
{
    int warp = (blockIdx.x * blockDim.x + threadIdx.x) >> 5;
    int lane = threadIdx.x & 31;
    const float4* feat;
    const int* off;
    const int* csr;
    float4* outm;
    int node;
    if (warp < NR) {
        feat = featR; off = off_r; csr = csr_r; outm = outR; node = warp;
    } else if (warp < NR + NU) {
        feat = featU; off = off_u; csr = csr_u; outm = outU; node = warp - NR;
    } else return;
    int b = off[node], e = off[node + 1];
    float4 acc = make_float4(0.f, 0.f, 0.f, 0.f);
    int i = b;
    for (; i + 4 <= e; i += 4) {
        int n0 = csr[i], n1 = csr[i + 1], n2 = csr[i + 2], n3 = csr[i + 3];
        float4 v0 = feat[(size_t)n0 * 32 + lane];
        float4 v1 = feat[(size_t)n1 * 32 + lane];
        float4 v2 = feat[(size_t)n2 * 32 + lane];
        float4 v3 = feat[(size_t)n3 * 32 + lane];
        acc.x += v0.x + v1.x + v2.x + v3.x;
        acc.y += v0.y + v1.y + v2.y + v3.y;
        acc.z += v0.z + v1.z + v2.z + v3.z;
        acc.w += v0.w + v1.w + v2.w + v3.w;
    }
    for (; i < e; i++) {
        int nb = csr[i];
        float4 v = feat[(size_t)nb * 32 + lane];
        acc.x += v.x; acc.y += v.y; acc.z += v.z; acc.w += v.w;
    }
    float inv = 1.f / fmaxf((float)(e - b), 1.f);
    acc.x *= inv; acc.y *= inv; acc.z *= inv; acc.w *= inv;
    outm[(size_t)node * 32 + lane] = acc;
}

// ---------------- fused 64-dim gather + bias + root + NORMALIZE ----------------
__global__ __launch_bounds__(256) void gather2_64f(
    const float2* __restrict__ U2, const float2* __restrict__ R2,
    const float* __restrict__ bl_ur, const float* __restrict__ bl_ru,
    const int* __restrict__ off_r, const int* __restrict__ csr_r,
    const int* __restrict__ off_u, const int* __restrict__ csr_u,
    float2* __restrict__ zr, float2* __restrict__ zu)
{
    int warp = (blockIdx.x * blockDim.x + threadIdx.x) >> 5;
    int lane = threadIdx.x & 31;
    const float2* feat;
    const float2* selfp;
    const float2* bl;
    const int* off;
    const int* csr;
    float2* outp;
    int node;
    if (warp < NR) {
        node = warp;
        feat = U2; selfp = R2; bl = (const float2*)bl_ur;
        off = off_r; csr = csr_r; outp = zr;
    } else if (warp < NR + NU) {
        node = warp - NR;
        feat = R2; selfp = U2; bl = (const float2*)bl_ru;
        off = off_u; csr = csr_u; outp = zu;
    } else return;
    int b = off[node], e = off[node + 1];
    float2 acc = make_float2(0.f, 0.f);
    int i = b;
    for (; i + 4 <= e; i += 4) {
        int n0 = csr[i], n1 = csr[i + 1], n2 = csr[i + 2], n3 = csr[i + 3];
        float2 v0 = feat[(size_t)n0 * 64 + lane];
        float2 v1 = feat[(size_t)n1 * 64 + lane];
        float2 v2 = feat[(size_t)n2 * 64 + lane];
        float2 v3 = feat[(size_t)n3 * 64 + lane];
        acc.x += v0.x + v1.x + v2.x + v3.x;
        acc.y += v0.y + v1.y + v2.y + v3.y;
    }
    for (; i < e; i++) {
        int nb = csr[i];
        float2 v = feat[(size_t)nb * 64 + lane];
        acc.x += v.x; acc.y += v.y;
    }
    float inv = 1.f / fmaxf((float)(e - b), 1.f);
    float2 s = selfp[(size_t)node * 64 + 32 + lane];
    float2 bb = bl[lane];
    float2 o;
    o.x = acc.x * inv + bb.x + s.x;
    o.y = acc.y * inv + bb.y + s.y;
    float nsum = o.x * o.x + o.y * o.y;
#pragma unroll
    for (int ofs = 16; ofs; ofs >>= 1)
        nsum += __shfl_xor_sync(0xffffffffu, nsum, ofs);
    float innorm = 1.f / fmaxf(sqrtf(nsum), 1e-12f);
    o.x *= innorm; o.y *= innorm;
    outp[(size_t)node * 32 + lane] = o;
}

// ---------------- FFMA2 mainloop (style A, proven) ----------------
template <int N, int K, bool DUAL>
__device__ __forceinline__ void mm_acc(
    const float* __restrict__ sA, const float* __restrict__ sX,
    const float* __restrict__ sWl, const float* __restrict__ sWr,
    int r0, int colbase, u64 acc[8][N / 64])
{
    constexpr int CPT = N / 32;
    constexpr int PAIRS = CPT / 2;
#pragma unroll 2
    for (int k0 = 0; k0 < K; k0 += 4) {
        float4 a4[8], x4[8];
#pragma unroll
        for (int i = 0; i < 8; i++) {
            a4[i] = *(const float4*)&sA[(r0 + i) * K + k0];
            if (DUAL) x4[i] = *(const float4*)&sX[(r0 + i) * K + k0];
        }
#pragma unroll
        for (int kk = 0; kk < 4; kk++) {
            u64 wl[PAIRS], wr[PAIRS];
            const float* wlp = &sWl[(k0 + kk) * N + colbase];
            if (CPT == 4) {
                float4 v = *(const float4*)wlp;
                wl[0] = pack2(v.x, v.y);
                if (PAIRS > 1) wl[1] = pack2(v.z, v.w);
            } else {
                float2 v = *(const float2*)wlp;
                wl[0] = pack2(v.x, v.y);
            }
            if (DUAL) {
                const float* wrp = &sWr[(k0 + kk) * N + colbase];
                if (CPT == 4) {
                    float4 v = *(const float4*)wrp;
                    wr[0] = pack2(v.x, v.y);
                    if (PAIRS > 1) wr[1] = pack2(v.z, v.w);
                } else {
                    float2 v = *(const float2*)wrp;
                    wr[0] = pack2(v.x, v.y);
                }
            }
#pragma unroll
            for (int i = 0; i < 8; i++) {
                float as = (kk == 0) ? a4[i].x : (kk == 1) ? a4[i].y :
                           (kk == 2) ? a4[i].z : a4[i].w;
                u64 a2 = pack2(as, as);
#pragma unroll
                for (int p = 0; p < PAIRS; p++) acc[i][p] = fma2(a2, wl[p], acc[i][p]);
                if (DUAL) {
                    float xs = (kk == 0) ? x4[i].x : (kk == 1) ? x4[i].y :
                               (kk == 2) ? x4[i].z : x4[i].w;
                    u64 x2 = pack2(xs, xs);
#pragma unroll
                    for (int p = 0; p < PAIRS; p++) acc[i][p] = fma2(x2, wr[p], acc[i][p]);
                }
            }
        }
    }
}

// ---------------- persistent FFMA2 GEMM (conv layers) ----------------
template <int N, int K, bool DUAL, bool ADDIN, bool HASB, bool RELU>
__global__ __launch_bounds__(256) void gemm_k(
    const float* __restrict__ A, const float* __restrict__ X,
    const float* __restrict__ Wlt, const float* __restrict__ Wrt,
    const float* __restrict__ bl, const float* __restrict__ ADDP,
    float* __restrict__ Y, int M)
{
    constexpr int CPT = N / 32;
    constexpr int PAIRS = CPT / 2;
    extern __shared__ float sm[];
    float* sWl = sm;
    float* sWr = sm + K * N;
    float* sA  = sm + (DUAL ? 2 : 1) * K * N;
    float* sX  = sA + 64 * K;

    const int tid = threadIdx.x;

    {
        const float4* w4 = (const float4*)Wlt;
        float4* s4 = (float4*)sWl;
        for (int i = tid; i < K * N / 4; i += 256) s4[i] = w4[i];
        if (DUAL) {
            const float4* v4 = (const float4*)Wrt;
            float4* t4 = (float4*)sWr;
            for (int i = tid; i < K * N / 4; i += 256) t4[i] = v4[i];
        }
    }

    const int lane = tid & 31;
    const int w = tid >> 5;
    const int r0 = w * 8;
    const int colbase = lane * CPT;

    float bv[CPT];
#pragma unroll
    for (int j = 0; j < CPT; j++) bv[j] = HASB ? bl[colbase + j] : 0.f;

    const int ntiles = (M + 63) >> 6;
    for (int tile = blockIdx.x; tile < ntiles; tile += gridDim.x) {
        const int row0 = tile << 6;
        __syncthreads();
        {
            int lim = min(64, M - row0) * (K / 4);
            const float4* A4 = (const float4*)(A + (size_t)row0 * K);
            float4* sA4 = (float4*)sA;
            const float4* X4 = DUAL ? (const float4*)(X + (size_t)row0 * K) : nullptr;
            float4* sX4 = (float4*)sX;
            for (int i = tid; i < 64 * K / 4; i += 256) {
                float4 v = (i < lim) ? A4[i] : make_float4(0.f, 0.f, 0.f, 0.f);
                sA4[i] = v;
                if (DUAL) {
                    float4 u = (i < lim) ? X4[i] : make_float4(0.f, 0.f, 0.f, 0.f);
                    sX4[i] = u;
                }
            }
        }
        __syncthreads();

        u64 acc[8][PAIRS];
#pragma unroll
        for (int i = 0; i < 8; i++)
#pragma unroll
            for (int p = 0; p < PAIRS; p++) acc[i][p] = 0ull;

        mm_acc<N, K, DUAL>(sA, sX, sWl, sWr, r0, colbase, acc);

#pragma unroll
        for (int i = 0; i < 8; i++) {
            int row = row0 + r0 + i;
            if (row < M) {
                float o[CPT];
#pragma unroll
                for (int p = 0; p < PAIRS; p++) {
                    float2 v = unpack2(acc[i][p]);
                    o[2 * p] = v.x + bv[2 * p];
                    o[2 * p + 1] = v.y + bv[2 * p + 1];
                }
                if (ADDIN) {
                    const float* ap = &ADDP[(size_t)row * N + colbase];
                    if (CPT == 4) {
                        float4 v = *(const float4*)ap;
                        o[0] += v.x; o[1] += v.y; o[2] += v.z; o[3] += v.w;
                    } else {
                        float2 v = *(const float2*)ap;
                        o[0] += v.x; o[1] += v.y;
                    }
                }
                if (RELU) {
#pragma unroll
                    for (int j = 0; j < CPT; j++) o[j] = fmaxf(o[j], 0.f);
                }
                float* yp = &Y[(size_t)row * N + colbase];
                if (CPT == 4) *(float4*)yp = make_float4(o[0], o[1], o[2], o[3]);
                else          *(float2*)yp = make_float2(o[0], o[1]);
            }
        }
    }
}

// ---------------- decoder: dot of pre-normalized rows ----------------
__global__ __launch_bounds__(256) void decode_kernel(
    const float2* __restrict__ zu, const float2* __restrict__ zr,
    const int* __restrict__ ls, const int* __restrict__ ld,
    float* __restrict__ out, int L)
{
    int warp = (blockIdx.x * blockDim.x + threadIdx.x) >> 5;
    int lane = threadIdx.x & 31;
    if (warp >= L) return;
    int s = ls[warp], d = ld[warp];
    float2 a = zu[(size_t)s * 32 + lane];
    float2 b = zr[(size_t)d * 32 + lane];
    float dot = a.x * b.x + a.y * b.y;
#pragma unroll
    for (int o = 16; o; o >>= 1)
        dot += __shfl_xor_sync(0xffffffffu, dot, o);
    if (lane == 0)
        out[warp] = dot;
}

// ---------------- host launch ----------------
extern "C" void kernel_launch(void* const* d_in, const int* in_sizes, int n_in,
                              void* d_out, int out_size)
{
    const float* x_user   = (const float*)d_in[0];
    const float* x_recipe = (const float*)d_in[1];
    const int* edge_src   = (const int*)d_in[2];
    const int* edge_dst   = (const int*)d_in[3];
    const int* lbl_src    = (const int*)d_in[4];
    const int* lbl_dst    = (const int*)d_in[5];
    const float* Wu   = (const float*)d_in[6];
    const float* bu   = (const float*)d_in[7];
    const float* Wrec = (const float*)d_in[8];
    const float* brec = (const float*)d_in[9];
    const float* c1_ur_Wl = (const float*)d_in[10];
    const float* c1_ur_bl = (const float*)d_in[11];
    const float* c1_ur_Wr = (const float*)d_in[12];
    const float* c1_ru_Wl = (const float*)d_in[13];
    const float* c1_ru_bl = (const float*)d_in[14];
    const float* c1_ru_Wr = (const float*)d_in[15];
    const float* c2_ur_Wl = (const float*)d_in[16];
    const float* c2_ur_bl = (const float*)d_in[17];
    const float* c2_ur_Wr = (const float*)d_in[18];
    const float* c2_ru_Wl = (const float*)d_in[19];
    const float* c2_ru_bl = (const float*)d_in[20];
    const float* c2_ru_Wr = (const float*)d_in[21];
    float* out = (float*)d_out;

    float *hu, *hr, *p1, *u1, *r1, *mu, *mr, *zu, *zr, *wt;
    __nv_bfloat16 *wbh, *wbl;
    int *deg_r, *deg_u, *off_r, *off_u, *cur_r, *cur_u, *csr_r, *csr_u;
    cudaGetSymbolAddress((void**)&hu, g_hu);
    cudaGetSymbolAddress((void**)&hr, g_hr);
    cudaGetSymbolAddress((void**)&p1, g_p1);
    cudaGetSymbolAddress((void**)&u1, g_u1);
    cudaGetSymbolAddress((void**)&r1, g_r1);
    cudaGetSymbolAddress((void**)&mu, g_mean_u);
    cudaGetSymbolAddress((void**)&mr, g_mean_r);
    cudaGetSymbolAddress((void**)&zu, g_zu);
    cudaGetSymbolAddress((void**)&zr, g_zr);
    cudaGetSymbolAddress((void**)&wt, g_wt);
    cudaGetSymbolAddress((void**)&wbh, g_wbh);
    cudaGetSymbolAddress((void**)&wbl, g_wbl);
    cudaGetSymbolAddress((void**)&deg_r, g_deg_r);
    cudaGetSymbolAddress((void**)&deg_u, g_deg_u);
    cudaGetSymbolAddress((void**)&off_r, g_off_r);
    cudaGetSymbolAddress((void**)&off_u, g_off_u);
    cudaGetSymbolAddress((void**)&cur_r, g_cur_r);
    cudaGetSymbolAddress((void**)&cur_u, g_cur_u);
    cudaGetSymbolAddress((void**)&csr_r, g_csr_r);
    cudaGetSymbolAddress((void**)&csr_u, g_csr_u);

    static cudaStream_t side = nullptr, s2 = nullptr;
    static cudaEvent_t evF = nullptr, evJ = nullptr, evG = nullptr, evA = nullptr;
    if (side == nullptr) {
        cudaStreamCreateWithFlags(&side, cudaStreamNonBlocking);
        cudaStreamCreateWithFlags(&s2, cudaStreamNonBlocking);
        cudaEventCreateWithFlags(&evF, cudaEventDisableTiming);
        cudaEventCreateWithFlags(&evJ, cudaEventDisableTiming);
        cudaEventCreateWithFlags(&evG, cudaEventDisableTiming);
        cudaEventCreateWithFlags(&evA, cudaEventDisableTiming);
    }

    const int S_P128 = (128 * 128 + 64 * 128) * 4;           // 98304 (FFMA2)
    const int S_D128 = (2 * 128 * 128 + 2 * 64 * 128) * 4;   // 196608 (FFMA2 dual)
    const int S_W128 = (2 * 128 * 136 + 2 * 64 * 136) * 2;   // 104448 (wmma K=128)
    const int S_W256 = (2 * 128 * 264 + 2 * 64 * 264) * 2;   // 202752 (wmma K=256)

    cudaFuncSetAttribute((gemm_wmma<128, true>),
                         cudaFuncAttributeMaxDynamicSharedMemorySize, S_W128);
    cudaFuncSetAttribute((gemm_wmma<128, false>),
                         cudaFuncAttributeMaxDynamicSharedMemorySize, S_W128);
    cudaFuncSetAttribute((gemm_wmma<256, true>),
                         cudaFuncAttributeMaxDynamicSharedMemorySize, S_W256);
    cudaFuncSetAttribute((gemm_k<128, 128, false, false, false, false>),
                         cudaFuncAttributeMaxDynamicSharedMemorySize, S_P128);
    cudaFuncSetAttribute((gemm_k<128, 128, true,  false, true,  true>),
                         cudaFuncAttributeMaxDynamicSharedMemorySize, S_D128);
    cudaFuncSetAttribute((gemm_k<128, 128, false, true,  true,  true>),
                         cudaFuncAttributeMaxDynamicSharedMemorySize, S_P128);

    // ---- fork: CSR on side stream ----
    cudaEventRecord(evF, 0);
    cudaStreamWaitEvent(side, evF, 0);
    zero_deg<<<(NU + 255) / 256, 256, 0, side>>>(deg_u, deg_r);
    count_kernel<<<(NE + 255) / 256, 256, 0, side>>>(edge_src, edge_dst, deg_u, deg_r, NE);
    scan2_kernel<<<2, 1024, 0, side>>>(deg_r, off_r, cur_r, deg_u, off_u, cur_u);
    fill_kernel<<<(NE + 255) / 256, 256, 0, side>>>(edge_src, edge_dst, cur_u, cur_r,
                                                    csr_u, csr_r, NE);
    cudaEventRecord(evJ, side);

    // ---- main: weight prep ----
    {
        WtArgs a;
        const float* srcs[7] = {c1_ur_Wl, c1_ur_Wr, c1_ru_Wr,
                                c2_ur_Wl, c2_ru_Wr, c2_ru_Wl, c2_ur_Wr};
        int ns[7]    = {128, 128, 128, 64, 64, 64, 64};
        int ks[7]    = {128, 128, 128, 128, 128, 128, 128};
        int dn[7]    = {128, 128, 128, 128, 128, 128, 128};
        int co[7]    = {0, 0, 0, 0, 64, 0, 64};
        int doffs[7] = {WT_C1URWL, WT_C1URWR, WT_C1RUWR, WT_U2, WT_U2, WT_R2, WT_R2};
        int boff = 0;
        for (int m = 0; m < 7; m++) {
            a.src[m] = srcs[m]; a.n[m] = ns[m]; a.k[m] = ks[m];
            a.dstN[m] = dn[m]; a.coloff[m] = co[m]; a.doff[m] = doffs[m];
            a.blk_off[m] = boff;
            boff += (ns[m] * ks[m] + 255) / 256;
        }
        a.blk_off[7] = boff;
        wtrans_kernel<<<boff, 256>>>(a, wt);
    }
    {
        WbArgs a;
        const float* srcs[3] = {Wu, Wrec, c1_ru_Wl};
        int ns[3] = {128, 128, 128};
        int ks[3] = {128, 256, 128};
        int kp[3] = {136, 264, 136};
        int doffs[3] = {WB_WU, WB_WREC, WB_P1};
        int boff = 0;
        for (int m = 0; m < 3; m++) {
            a.src[m] = srcs[m]; a.n[m] = ns[m]; a.k[m] = ks[m]; a.kp[m] = kp[m];
            a.doff[m] = doffs[m];
            a.blk_off[m] = boff;
            boff += (ns[m] * kp[m] + 255) / 256;
        }
        a.blk_off[3] = boff;
        wconv_kernel<<<boff, 256>>>(a, wbh, wbl);
    }

    // ---- projections (wmma split-bf16) ----
    gemm_wmma<128, true><<<296, 256, S_W128>>>(
        x_user, wbh + WB_WU, wbl + WB_WU, bu, hu, NU);
    gemm_wmma<256, true><<<148, 256, S_W256>>>(
        x_recipe, wbh + WB_WREC, wbl + WB_WREC, brec, hr, NR);
    gemm_wmma<128, false><<<296, 256, S_W128>>>(
        hr, wbh + WB_P1, wbl + WB_P1, nullptr, p1, NR);

    // ---- join CSR; conv1 gather ----
    cudaStreamWaitEvent(0, evJ, 0);
    const int GW = ((NR + NU) * 32 + 255) / 256;
    gather2_128<<<GW, 256>>>((const float4*)hu, (const float4*)p1,
                             off_r, csr_r, off_u, csr_u,
                             (float4*)mr, (float4*)mu);
    cudaEventRecord(evG, 0);

    // ---- chain A on s2: r1 (dual) -> R2 ----
    cudaStreamWaitEvent(s2, evG, 0);
    gemm_k<128, 128, true, false, true, true><<<148, 256, S_D128, s2>>>(
        mr, hr, wt + WT_C1URWL, wt + WT_C1URWR, c1_ur_bl, nullptr, r1, NR);
    gemm_k<128, 128, false, false, false, false><<<296, 256, S_P128, s2>>>(
        r1, nullptr, wt + WT_R2, nullptr, nullptr, nullptr, mr, NR);
    cudaEventRecord(evA, s2);

    // ---- chain B on main: u1 (ADDIN mu) -> U2 ----
    gemm_k<128, 128, false, true, true, true><<<296, 256, S_P128>>>(
        hu, nullptr, wt + WT_C1RUWR, nullptr, c1_ru_bl, mu, u1, NU);
    gemm_k<128, 128, false, false, false, false><<<296, 256, S_P128>>>(
        u1, nullptr, wt + WT_U2, nullptr, nullptr, nullptr, mu, NU);

    // ---- join; fused conv2 gather (normalized outputs) ----
    cudaStreamWaitEvent(0, evA, 0);
    gather2_64f<<<GW, 256>>>((const float2*)mu, (const float2*)mr,
                             c2_ur_bl, c2_ru_bl,
                             off_r, csr_r, off_u, csr_u,
                             (float2*)zr, (float2*)zu);

    // ---- decoder ----
    decode_kernel<<<(NL * 32 + 255) / 256, 256>>>(
        (const float2*)zu, (const float2*)zr, lbl_src, lbl_dst, out, NL);
}

// round 9
// speedup vs baseline: 1.5125x; 1.0942x over previous
#include <cuda_runtime.h>
#include <cuda_bf16.h>
#include <mma.h>
#include <math.h>

using namespace nvcuda;

#define NU 100000
#define NR 50000
#define NE 600000
#define NL 200000
#define HD 128
#define OD 64

// ---------------- scratch ----------------
__device__ __align__(16) float g_hu[(size_t)NU * HD];
__device__ __align__(16) float g_hr[(size_t)NR * HD];
__device__ __align__(16) float g_p1[(size_t)NR * HD];
__device__ __align__(16) float g_u1[(size_t)NU * HD];
__device__ __align__(16) float g_r1[(size_t)NR * HD];
__device__ __align__(16) float g_mean_u[(size_t)NU * HD]; // mu, then U2
__device__ __align__(16) float g_mean_r[(size_t)NR * HD]; // mr, then R2
__device__ __align__(16) float g_zu[(size_t)NU * OD];
__device__ __align__(16) float g_zr[(size_t)NR * OD];

// bf16 split weights, all padded [N][K+8] row-major
__device__ __align__(16) __nv_bfloat16 g_wbh[154624];
__device__ __align__(16) __nv_bfloat16 g_wbl[154624];
#define WB_WU      0        // Wu        [128][136]
#define WB_WREC    17408    // Wrec      [128][264]
#define WB_P1      51200    // c1_ru_Wl  [128][136]
#define WB_C1UR    68608    // [c1_ur_Wl | c1_ur_Wr] stacked-K [128][264]
#define WB_C1RUWR  102400   // c1_ru_Wr  [128][136]
#define WB_U2      119808   // rows 0-63 c2_ur_Wl, 64-127 c2_ru_Wr  [128][136]
#define WB_R2      137216   // rows 0-63 c2_ru_Wl, 64-127 c2_ur_Wr  [128][136]

__device__ int g_deg_r[NR];
__device__ int g_deg_u[NU];
__device__ int g_off_r[NR + 1];
__device__ int g_off_u[NU + 1];
__device__ int g_cur_r[NR];
__device__ int g_cur_u[NU];
__device__ int g_csr_r[NE];
__device__ int g_csr_u[NE];

// ---------------- CSR build ----------------
__global__ void zero_deg(int* __restrict__ deg_u, int* __restrict__ deg_r)
{
    int t = blockIdx.x * blockDim.x + threadIdx.x;
    if (t < NU) deg_u[t] = 0;
    if (t < NR) deg_r[t] = 0;
}

__global__ void count_kernel(const int* __restrict__ es, const int* __restrict__ ed,
                             int* __restrict__ deg_u, int* __restrict__ deg_r, int E)
{
    int t = blockIdx.x * blockDim.x + threadIdx.x;
    if (t < E) {
        atomicAdd(&deg_u[es[t]], 1);
        atomicAdd(&deg_r[ed[t]], 1);
    }
}

__global__ void scan2_kernel(const int* __restrict__ deg_r, int* __restrict__ off_r,
                             int* __restrict__ cur_r,
                             const int* __restrict__ deg_u, int* __restrict__ off_u,
                             int* __restrict__ cur_u)
{
    const int* deg; int* off; int* cur; int n;
    if (blockIdx.x == 0) { deg = deg_r; off = off_r; cur = cur_r; n = NR; }
    else                 { deg = deg_u; off = off_u; cur = cur_u; n = NU; }
    __shared__ int tmp[1024];
    int t = threadIdx.x;
    int chunk = (n + 1023) / 1024;
    int start = min(t * chunk, n);
    int end = min(start + chunk, n);
    int s = 0;
    for (int i = start; i < end; i++) s += deg[i];
    tmp[t] = s;
    __syncthreads();
    for (int d = 1; d < 1024; d <<= 1) {
        int v = (t >= d) ? tmp[t - d] : 0;
        __syncthreads();
        tmp[t] += v;
        __syncthreads();
    }
    int run = (t == 0) ? 0 : tmp[t - 1];
    for (int i = start; i < end; i++) {
        off[i] = run;
        cur[i] = run;
        run += deg[i];
    }
    if (end == n) off[n] = run;
}

__global__ void fill_kernel(const int* __restrict__ es, const int* __restrict__ ed,
                            int* __restrict__ cur_u, int* __restrict__ cur_r,
                            int* __restrict__ csr_u, int* __restrict__ csr_r, int E)
{
    int t = blockIdx.x * blockDim.x + threadIdx.x;
    if (t < E) {
        int s = es[t], d = ed[t];
        int pr = atomicAdd(&cur_r[d], 1);
        csr_r[pr] = s;
        int pu = atomicAdd(&cur_u[s], 1);
        csr_u[pu] = d;
    }
}

// ---------------- bf16 split weight prep (all matrices) ----------------
struct WcArgs {
    const float* src[10];
    int nrows[10];
    int kcols[10];
    int cover[10];   // dst columns spanned (kcols data + optional zero pad)
    int pitch[10];   // dst row pitch
    int base[10];    // dst bf16 index
    int blk_off[11];
};

__global__ void wconv_kernel(WcArgs a, __nv_bfloat16* __restrict__ hi,
                             __nv_bfloat16* __restrict__ lo)
{
    int b = blockIdx.x;
    int m = 0;
    while (b >= a.blk_off[m + 1]) m++;
    int idx = (b - a.blk_off[m]) * 256 + threadIdx.x;
    int NR_ = a.nrows[m], KC = a.kcols[m], CV = a.cover[m];
    if (idx < NR_ * CV) {
        int r = idx / CV, c = idx - r * CV;
        float v = (c < KC) ? a.src[m][r * KC + c] : 0.f;
        __nv_bfloat16 h = __float2bfloat16(v);
        float rr = v - __bfloat162float(h);
        int d = a.base[m] + r * a.pitch[m] + c;
        hi[d] = h;
        lo[d] = __float2bfloat16(rr);
    }
}

// ---------------- wmma split-bf16 GEMM ----------------
// Y[M,128] = A[M,K]@W^T (+X appended as K cols 128..255 if DUAL) (+bl) (+ADDP) (+relu)
// W split hi/lo in [128][K+8] row-major (col-major B view).
template <int K, bool DUAL, bool ADDIN, bool HASB, bool RELU>
__global__ __launch_bounds__(256) void gemm_wmma(
    const float* __restrict__ A, const float* __restrict__ X,
    const __nv_bfloat16* __restrict__ Whi, const __nv_bfloat16* __restrict__ Wlo,
    const float* __restrict__ bl, const float* __restrict__ ADDP,
    float* __restrict__ Y, int M)
{
    constexpr int KP = K + 8;
    constexpr int QR = K / 4;        // float4 quads per (stacked) row
    extern __shared__ __nv_bfloat16 smemb[];
    __nv_bfloat16* sWhi = smemb;                 // 128*KP
    __nv_bfloat16* sWlo = sWhi + 128 * KP;       // 128*KP
    __nv_bfloat16* sAhi = sWlo + 128 * KP;       // 64*KP
    __nv_bfloat16* sAlo = sAhi + 64 * KP;        // 64*KP
    float* sOut = (float*)sAhi;                  // aliased after mainloop

    const int tid = threadIdx.x;

    {
        const uint4* src = (const uint4*)Whi;
        uint4* dst = (uint4*)sWhi;
        for (int i = tid; i < 128 * KP / 8; i += 256) dst[i] = src[i];
        const uint4* src2 = (const uint4*)Wlo;
        uint4* dst2 = (uint4*)sWlo;
        for (int i = tid; i < 128 * KP / 8; i += 256) dst2[i] = src2[i];
    }

    const int w = tid >> 5;
    const int mrow0 = (w >> 2) * 32;
    const int ncol0 = (w & 3) * 32;

    const int ntiles = (M + 63) >> 6;
    for (int tile = blockIdx.x; tile < ntiles; tile += gridDim.x) {
        const int row0 = tile << 6;
        __syncthreads();
        {
            int rows = min(64, M - row0);
            for (int i = tid; i < 64 * QR; i += 256) {
                int r = i / QR, q = i - r * QR;
                float4 v = make_float4(0.f, 0.f, 0.f, 0.f);
                if (r < rows) {
                    if (DUAL) {
                        v = (q < 32)
                          ? *(const float4*)(A + (size_t)(row0 + r) * 128 + 4 * q)
                          : *(const float4*)(X + (size_t)(row0 + r) * 128 + 4 * (q - 32));
                    } else {
                        v = *(const float4*)(A + (size_t)(row0 + r) * K + 4 * q);
                    }
                }
                float vv[4] = {v.x, v.y, v.z, v.w};
                unsigned ph0 = 0, ph1 = 0, pl0 = 0, pl1 = 0;
#pragma unroll
                for (int qq = 0; qq < 2; qq++) {
                    __nv_bfloat16 h = __float2bfloat16(vv[qq]);
                    __nv_bfloat16 l = __float2bfloat16(vv[qq] - __bfloat162float(h));
                    ph0 |= (unsigned)__bfloat16_as_ushort(h) << (16 * qq);
                    pl0 |= (unsigned)__bfloat16_as_ushort(l) << (16 * qq);
                }
#pragma unroll
                for (int qq = 0; qq < 2; qq++) {
                    __nv_bfloat16 h = __float2bfloat16(vv[2 + qq]);
                    __nv_bfloat16 l = __float2bfloat16(vv[2 + qq] - __bfloat162float(h));
                    ph1 |= (unsigned)__bfloat16_as_ushort(h) << (16 * qq);
                    pl1 |= (unsigned)__bfloat16_as_ushort(l) << (16 * qq);
                }
                *(uint2*)&sAhi[r * KP + 4 * q] = make_uint2(ph0, ph1);
                *(uint2*)&sAlo[r * KP + 4 * q] = make_uint2(pl0, pl1);
            }
        }
        __syncthreads();

        wmma::fragment<wmma::accumulator, 16, 16, 16, float> acc[2][2];
#pragma unroll
        for (int i = 0; i < 2; i++)
#pragma unroll
            for (int j = 0; j < 2; j++) wmma::fill_fragment(acc[i][j], 0.f);

        for (int k0 = 0; k0 < K; k0 += 16) {
            wmma::fragment<wmma::matrix_a, 16, 16, 16, __nv_bfloat16, wmma::row_major> ahi[2], alo[2];
            wmma::fragment<wmma::matrix_b, 16, 16, 16, __nv_bfloat16, wmma::col_major> bhi[2], blo[2];
#pragma unroll
            for (int i = 0; i < 2; i++) {
                wmma::load_matrix_sync(ahi[i], sAhi + (mrow0 + 16 * i) * KP + k0, KP);
                wmma::load_matrix_sync(alo[i], sAlo + (mrow0 + 16 * i) * KP + k0, KP);
            }
#pragma unroll
            for (int j = 0; j < 2; j++) {
                wmma::load_matrix_sync(bhi[j], sWhi + (ncol0 + 16 * j) * KP + k0, KP);
                wmma::load_matrix_sync(blo[j], sWlo + (ncol0 + 16 * j) * KP + k0, KP);
            }
#pragma unroll
            for (int i = 0; i < 2; i++)
#pragma unroll
                for (int j = 0; j < 2; j++) {
                    wmma::mma_sync(acc[i][j], ahi[i], bhi[j], acc[i][j]);
                    wmma::mma_sync(acc[i][j], ahi[i], blo[j], acc[i][j]);
                    wmma::mma_sync(acc[i][j], alo[i], bhi[j], acc[i][j]);
                }
        }

        __syncthreads();
#pragma unroll
        for (int i = 0; i < 2; i++)
#pragma unroll
            for (int j = 0; j < 2; j++)
                wmma::store_matrix_sync(sOut + (mrow0 + 16 * i) * 128 + ncol0 + 16 * j,
                                        acc[i][j], 128, wmma::mem_row_major);
        __syncthreads();

        {
            int rows = min(64, M - row0);
            for (int i = tid; i < 64 * 32; i += 256) {
                int r = i >> 5, c4 = i & 31;
                if (r < rows) {
                    float4 v = ((const float4*)sOut)[i];
                    if (HASB) {
                        float4 b4 = *(const float4*)(bl + 4 * c4);
                        v.x += b4.x; v.y += b4.y; v.z += b4.z; v.w += b4.w;
                    }
                    if (ADDIN) {
                        float4 a4 = *(const float4*)(ADDP + (size_t)(row0 + r) * 128 + 4 * c4);
                        v.x += a4.x; v.y += a4.y; v.z += a4.z; v.w += a4.w;
                    }
                    if (RELU) {
                        v.x = fmaxf(v.x, 0.f); v.y = fmaxf(v.y, 0.f);
                        v.z = fmaxf(v.z, 0.f); v.w = fmaxf(v.w, 0.f);
                    }
                    *(float4*)(Y + (size_t)(row0 + r) * 128 + 4 * c4) = v;
                }
            }
        }
    }
}

// ---------------- gather-mean 128-dim, warp/node, unroll-4 ----------------
__global__ __launch_bounds__(256) void gather2_128(
    const float4* __restrict__ featR, const float4* __restrict__ featU,
    const int* __restrict__ off_r, const int* __restrict__ csr_r,
    const int* __restrict__ off_u, const int* __restrict__ csr_u,
    float4* __restrict__ outR, float4* __restrict__ outU)
{
    int warp = (blockIdx.x * blockDim.x + threadIdx.x) >> 5;
    int lane = threadIdx.x & 31;
    const float4* feat;
    const int* off;
    const int* csr;
    float4* outm;
    int node;
    if (warp < NR) {
        feat = featR; off = off_r; csr = csr_r; outm = outR; node = warp;
    } else if (warp < NR + NU) {
        feat = featU; off = off_u; csr = csr_u; outm = outU; node = warp - NR;
    } else return;
    int b = off[node], e = off[node + 1];
    float4 acc = make_float4(0.f, 0.f, 0.f, 0.f);
    int i = b;
    for (; i + 4 <= e; i += 4) {
        int n0 = csr[i], n1 = csr[i + 1], n2 = csr[i + 2], n3 = csr[i + 3];
        float4 v0 = feat[(size_t)n0 * 32 + lane];
        float4 v1 = feat[(size_t)n1 * 32 + lane];
        float4 v2 = feat[(size_t)n2 * 32 + lane];
        float4 v3 = feat[(size_t)n3 * 32 + lane];
        acc.x += v0.x + v1.x + v2.x + v3.x;
        acc.y += v0.y + v1.y + v2.y + v3.y;
        acc.z += v0.z + v1.z + v2.z + v3.z;
        acc.w += v0.w + v1.w + v2.w + v3.w;
    }
    for (; i < e; i++) {
        int nb = csr[i];
        float4 v = feat[(size_t)nb * 32 + lane];
        acc.x += v.x; acc.y += v.y; acc.z += v.z; acc.w += v.w;
    }
    float inv = 1.f / fmaxf((float)(e - b), 1.f);
    acc.x *= inv; acc.y *= inv; acc.z *= inv; acc.w *= inv;
    outm[(size_t)node * 32 + lane] = acc;
}

// ---------------- fused 64-dim gather + bias + root + NORMALIZE ----------------
__global__ __launch_bounds__(256) void gather2_64f(
    const float2* __restrict__ U2, const float2* __restrict__ R2,
    const float* __restrict__ bl_ur, const float* __restrict__ bl_ru,
    const int* __restrict__ off_r, const int* __restrict__ csr_r,
    const int* __restrict__ off_u, const int* __restrict__ csr_u,
    float2* __restrict__ zr, float2* __restrict__ zu)
{
    int warp = (blockIdx.x * blockDim.x + threadIdx.x) >> 5;
    int lane = threadIdx.x & 31;
    const float2* feat;
    const float2* selfp;
    const float2* bl;
    const int* off;
    const int* csr;
    float2* outp;
    int node;
    if (warp < NR) {
        node = warp;
        feat = U2; selfp = R2; bl = (const float2*)bl_ur;
        off = off_r; csr = csr_r; outp = zr;
    } else if (warp < NR + NU) {
        node = warp - NR;
        feat = R2; selfp = U2; bl = (const float2*)bl_ru;
        off = off_u; csr = csr_u; outp = zu;
    } else return;
    int b = off[node], e = off[node + 1];
    float2 acc = make_float2(0.f, 0.f);
    int i = b;
    for (; i + 4 <= e; i += 4) {
        int n0 = csr[i], n1 = csr[i + 1], n2 = csr[i + 2], n3 = csr[i + 3];
        float2 v0 = feat[(size_t)n0 * 64 + lane];
        float2 v1 = feat[(size_t)n1 * 64 + lane];
        float2 v2 = feat[(size_t)n2 * 64 + lane];
        float2 v3 = feat[(size_t)n3 * 64 + lane];
        acc.x += v0.x + v1.x + v2.x + v3.x;
        acc.y += v0.y + v1.y + v2.y + v3.y;
    }
    for (; i < e; i++) {
        int nb = csr[i];
        float2 v = feat[(size_t)nb * 64 + lane];
        acc.x += v.x; acc.y += v.y;
    }
    float inv = 1.f / fmaxf((float)(e - b), 1.f);
    float2 s = selfp[(size_t)node * 64 + 32 + lane];
    float2 bb = bl[lane];
    float2 o;
    o.x = acc.x * inv + bb.x + s.x;
    o.y = acc.y * inv + bb.y + s.y;
    float nsum = o.x * o.x + o.y * o.y;
#pragma unroll
    for (int ofs = 16; ofs; ofs >>= 1)
        nsum += __shfl_xor_sync(0xffffffffu, nsum, ofs);
    float innorm = 1.f / fmaxf(sqrtf(nsum), 1e-12f);
    o.x *= innorm; o.y *= innorm;
    outp[(size_t)node * 32 + lane] = o;
}

// ---------------- decoder: dot of pre-normalized rows ----------------
__global__ __launch_bounds__(256) void decode_kernel(
    const float2* __restrict__ zu, const float2* __restrict__ zr,
    const int* __restrict__ ls, const int* __restrict__ ld,
    float* __restrict__ out, int L)
{
    int warp = (blockIdx.x * blockDim.x + threadIdx.x) >> 5;
    int lane = threadIdx.x & 31;
    if (warp >= L) return;
    int s = ls[warp], d = ld[warp];
    float2 a = zu[(size_t)s * 32 + lane];
    float2 b = zr[(size_t)d * 32 + lane];
    float dot = a.x * b.x + a.y * b.y;
#pragma unroll
    for (int o = 16; o; o >>= 1)
        dot += __shfl_xor_sync(0xffffffffu, dot, o);
    if (lane == 0)
        out[warp] = dot;
}

// ---------------- host launch ----------------
extern "C" void kernel_launch(void* const* d_in, const int* in_sizes, int n_in,
                              void* d_out, int out_size)
{
    const float* x_user   = (const float*)d_in[0];
    const float* x_recipe = (const float*)d_in[1];
    const int* edge_src   = (const int*)d_in[2];
    const int* edge_dst   = (const int*)d_in[3];
    const int* lbl_src    = (const int*)d_in[4];
    const int* lbl_dst    = (const int*)d_in[5];
    const float* Wu   = (const float*)d_in[6];
    const float* bu   = (const float*)d_in[7];
    const float* Wrec = (const float*)d_in[8];
    const float* brec = (const float*)d_in[9];
    const float* c1_ur_Wl = (const float*)d_in[10];
    const float* c1_ur_bl = (const float*)d_in[11];
    const float* c1_ur_Wr = (const float*)d_in[12];
    const float* c1_ru_Wl = (const float*)d_in[13];
    const float* c1_ru_bl = (const float*)d_in[14];
    const float* c1_ru_Wr = (const float*)d_in[15];
    const float* c2_ur_Wl = (const float*)d_in[16];
    const float* c2_ur_bl = (const float*)d_in[17];
    const float* c2_ur_Wr = (const float*)d_in[18];
    const float* c2_ru_Wl = (const float*)d_in[19];
    const float* c2_ru_bl = (const float*)d_in[20];
    const float* c2_ru_Wr = (const float*)d_in[21];
    float* out = (float*)d_out;

    float *hu, *hr, *p1, *u1, *r1, *mu, *mr, *zu, *zr;
    __nv_bfloat16 *wbh, *wbl;
    int *deg_r, *deg_u, *off_r, *off_u, *cur_r, *cur_u, *csr_r, *csr_u;
    cudaGetSymbolAddress((void**)&hu, g_hu);
    cudaGetSymbolAddress((void**)&hr, g_hr);
    cudaGetSymbolAddress((void**)&p1, g_p1);
    cudaGetSymbolAddress((void**)&u1, g_u1);
    cudaGetSymbolAddress((void**)&r1, g_r1);
    cudaGetSymbolAddress((void**)&mu, g_mean_u);
    cudaGetSymbolAddress((void**)&mr, g_mean_r);
    cudaGetSymbolAddress((void**)&zu, g_zu);
    cudaGetSymbolAddress((void**)&zr, g_zr);
    cudaGetSymbolAddress((void**)&wbh, g_wbh);
    cudaGetSymbolAddress((void**)&wbl, g_wbl);
    cudaGetSymbolAddress((void**)&deg_r, g_deg_r);
    cudaGetSymbolAddress((void**)&deg_u, g_deg_u);
    cudaGetSymbolAddress((void**)&off_r, g_off_r);
    cudaGetSymbolAddress((void**)&off_u, g_off_u);
    cudaGetSymbolAddress((void**)&cur_r, g_cur_r);
    cudaGetSymbolAddress((void**)&cur_u, g_cur_u);
    cudaGetSymbolAddress((void**)&csr_r, g_csr_r);
    cudaGetSymbolAddress((void**)&csr_u, g_csr_u);

    static cudaStream_t side = nullptr, s2 = nullptr;
    static cudaEvent_t evF = nullptr, evJ = nullptr, evG = nullptr, evA = nullptr;
    if (side == nullptr) {
        cudaStreamCreateWithFlags(&side, cudaStreamNonBlocking);
        cudaStreamCreateWithFlags(&s2, cudaStreamNonBlocking);
        cudaEventCreateWithFlags(&evF, cudaEventDisableTiming);
        cudaEventCreateWithFlags(&evJ, cudaEventDisableTiming);
        cudaEventCreateWithFlags(&evG, cudaEventDisableTiming);
        cudaEventCreateWithFlags(&evA, cudaEventDisableTiming);
    }

    const int S_W128 = (2 * 128 * 136 + 2 * 64 * 136) * 2;   // 104448
    const int S_W256 = (2 * 128 * 264 + 2 * 64 * 264) * 2;   // 202752

    cudaFuncSetAttribute((gemm_wmma<128, false, false, true,  false>),
                         cudaFuncAttributeMaxDynamicSharedMemorySize, S_W128);
    cudaFuncSetAttribute((gemm_wmma<256, false, false, true,  false>),
                         cudaFuncAttributeMaxDynamicSharedMemorySize, S_W256);
    cudaFuncSetAttribute((gemm_wmma<128, false, false, false, false>),
                         cudaFuncAttributeMaxDynamicSharedMemorySize, S_W128);
    cudaFuncSetAttribute((gemm_wmma<256, true,  false, true,  true>),
                         cudaFuncAttributeMaxDynamicSharedMemorySize, S_W256);
    cudaFuncSetAttribute((gemm_wmma<128, false, true,  true,  true>),
                         cudaFuncAttributeMaxDynamicSharedMemorySize, S_W128);

    // ---- fork: CSR on side stream ----
    cudaEventRecord(evF, 0);
    cudaStreamWaitEvent(side, evF, 0);
    zero_deg<<<(NU + 255) / 256, 256, 0, side>>>(deg_u, deg_r);
    count_kernel<<<(NE + 255) / 256, 256, 0, side>>>(edge_src, edge_dst, deg_u, deg_r, NE);
    scan2_kernel<<<2, 1024, 0, side>>>(deg_r, off_r, cur_r, deg_u, off_u, cur_u);
    fill_kernel<<<(NE + 255) / 256, 256, 0, side>>>(edge_src, edge_dst, cur_u, cur_r,
                                                    csr_u, csr_r, NE);
    cudaEventRecord(evJ, side);

    // ---- main: bf16 split weight prep (all matrices, one launch) ----
    {
        WcArgs a;
        const float* srcs[10] = {Wu, Wrec, c1_ru_Wl,
                                 c1_ur_Wl, c1_ur_Wr,
                                 c1_ru_Wr,
                                 c2_ur_Wl, c2_ru_Wr,
                                 c2_ru_Wl, c2_ur_Wr};
        int nr[10] = {128, 128, 128, 128, 128, 128, 64, 64, 64, 64};
        int kc[10] = {128, 256, 128, 128, 128, 128, 128, 128, 128, 128};
        int cv[10] = {136, 264, 136, 128, 136, 136, 136, 136, 136, 136};
        int pt[10] = {136, 264, 136, 264, 264, 136, 136, 136, 136, 136};
        int bs[10] = {WB_WU, WB_WREC, WB_P1,
                      WB_C1UR, WB_C1UR + 128,
                      WB_C1RUWR,
                      WB_U2, WB_U2 + 64 * 136,
                      WB_R2, WB_R2 + 64 * 136};
        int boff = 0;
        for (int m = 0; m < 10; m++) {
            a.src[m] = srcs[m]; a.nrows[m] = nr[m]; a.kcols[m] = kc[m];
            a.cover[m] = cv[m]; a.pitch[m] = pt[m]; a.base[m] = bs[m];
            a.blk_off[m] = boff;
            boff += (nr[m] * cv[m] + 255) / 256;
        }
        a.blk_off[10] = boff;
        wconv_kernel<<<boff, 256>>>(a, wbh, wbl);
    }

    // ---- projections (wmma) ----
    gemm_wmma<128, false, false, true, false><<<296, 256, S_W128>>>(
        x_user, nullptr, wbh + WB_WU, wbl + WB_WU, bu, nullptr, hu, NU);
    gemm_wmma<256, false, false, true, false><<<148, 256, S_W256>>>(
        x_recipe, nullptr, wbh + WB_WREC, wbl + WB_WREC, brec, nullptr, hr, NR);
    gemm_wmma<128, false, false, false, false><<<296, 256, S_W128>>>(
        hr, nullptr, wbh + WB_P1, wbl + WB_P1, nullptr, nullptr, p1, NR);

    // ---- join CSR; conv1 gather ----
    cudaStreamWaitEvent(0, evJ, 0);
    const int GW = ((NR + NU) * 32 + 255) / 256;
    gather2_128<<<GW, 256>>>((const float4*)hu, (const float4*)p1,
                             off_r, csr_r, off_u, csr_u,
                             (float4*)mr, (float4*)mu);
    cudaEventRecord(evG, 0);

    // ---- chain A on s2: r1 (stacked dual wmma) -> R2 ----
    cudaStreamWaitEvent(s2, evG, 0);
    gemm_wmma<256, true, false, true, true><<<148, 256, S_W256, s2>>>(
        mr, hr, wbh + WB_C1UR, wbl + WB_C1UR, c1_ur_bl, nullptr, r1, NR);
    gemm_wmma<128, false, false, false, false><<<296, 256, S_W128, s2>>>(
        r1, nullptr, wbh + WB_R2, wbl + WB_R2, nullptr, nullptr, mr, NR);
    cudaEventRecord(evA, s2);

    // ---- chain B on main: u1 (wmma, ADDIN mu) -> U2 ----
    gemm_wmma<128, false, true, true, true><<<296, 256, S_W128>>>(
        hu, nullptr, wbh + WB_C1RUWR, wbl + WB_C1RUWR, c1_ru_bl, mu, u1, NU);
    gemm_wmma<128, false, false, false, false><<<296, 256, S_W128>>>(
        u1, nullptr, wbh + WB_U2, wbl + WB_U2, nullptr, nullptr, mu, NU);

    // ---- join; fused conv2 gather (normalized outputs) ----
    cudaStreamWaitEvent(0, evA, 0);
    gather2_64f<<<GW, 256>>>((const float2*)mu, (const float2*)mr,
                             c2_ur_bl, c2_ru_bl,
                             off_r, csr_r, off_u, csr_u,
                             (float2*)zr, (float2*)zu);

    // ---- decoder ----
    decode_kernel<<<(NL * 32 + 255) / 256, 256>>>(
        (const float2*)zu, (const float2*)zr, lbl_src, lbl_dst, out, NL);
}